// round 5
// baseline (speedup 1.0000x reference)
#include <cuda_runtime.h>
#include <cuda_bf16.h>
#include <math.h>

// Problem constants
#define BATCH 4
#define CCH   1024          // C
#define DCH   128           // D = C/8
#define RCH   64            // R = C/16
#define NPIX  4096          // H*W

// ---------------------------------------------------------------------------
// Scratch (device globals: allocation-free per harness rules)
// ---------------------------------------------------------------------------
__device__ float g_Q  [(size_t)BATCH * DCH * NPIX];              // 8 MB
__device__ float g_K  [(size_t)BATCH * DCH * NPIX];              // 8 MB
__device__ float g_V  [(size_t)BATCH * CCH * NPIX];              // 64 MB
__device__ float g_att[(size_t)BATCH * NPIX * NPIX];             // 268 MB: att[b][m][n] = sigmoid(K_m . Q_n)
__device__ float g_outpre[(size_t)BATCH * CCH * NPIX];           // 64 MB (pre-gate out)
__device__ float g_pool[2 * BATCH * CCH];                        // [0]: avg rows, [BATCH*CCH]: max rows
__device__ float g_gate[BATCH * CCH];

// ---------------------------------------------------------------------------
// Generic tiled SGEMM:
//   C[o, n] = act( sum_k A[o*sAo + k*sAk] * B[k*Ndim + n]  + bias[o] )
// A strides allow both row-major [O,K] (sAk==1) and "transposed" [K,O] (sAo==1).
// B is always row-major [K, N]. Batched via per-operand batch strides.
// Tiles: 128x128x16, 256 threads, 8x8 per thread (4+4 split for LDS.128).
// All dims are exact multiples of tiles -> no predication.
// ---------------------------------------------------------------------------
#define TILE 128
#define BKD  16

__global__ __launch_bounds__(256)
void sgemm_kernel(int Ndim, int Kdim,
                  const float* __restrict__ Aall, long long sAo, long long sAk, long long sAb,
                  const float* __restrict__ Ball, long long sBb,
                  const float* __restrict__ bias,
                  float* __restrict__ Call, long long sCb,
                  int act)   // 0 = none, 1 = sigmoid
{
    __shared__ float As[BKD][TILE];
    __shared__ float Bs[BKD][TILE];

    const int bn = blockIdx.x * TILE;
    const int bm = blockIdx.y * TILE;
    const int b  = blockIdx.z;

    const float* A = Aall + (long long)b * sAb;
    const float* B = Ball + (long long)b * sBb;
    float*       C = Call + (long long)b * sCb;

    const int tid = threadIdx.x;
    const int tx  = tid & 15;   // n-dim
    const int ty  = tid >> 4;   // o-dim

    float acc[8][8];
#pragma unroll
    for (int i = 0; i < 8; i++)
#pragma unroll
        for (int j = 0; j < 8; j++) acc[i][j] = 0.f;

    const bool a_kontig = (sAk == 1);

    for (int k0 = 0; k0 < Kdim; k0 += BKD) {
        // ---- load A tile (TILE o  x  BKD k) into As[k][o]
        if (a_kontig) {
#pragma unroll
            for (int i = tid; i < TILE * BKD; i += 256) {
                int o = i >> 4, k = i & 15;
                As[k][o] = A[(long long)(bm + o) * sAo + (k0 + k)];
            }
        } else {
#pragma unroll
            for (int i = tid; i < TILE * BKD; i += 256) {
                int o = i & 127, k = i >> 7;
                As[k][o] = A[(long long)(bm + o) + (long long)(k0 + k) * sAk];
            }
        }
        // ---- load B tile (BKD k x TILE n), coalesced
#pragma unroll
        for (int i = tid; i < BKD * TILE; i += 256) {
            int k = i >> 7, n = i & 127;
            Bs[k][n] = B[(long long)(k0 + k) * Ndim + (bn + n)];
        }
        __syncthreads();

#pragma unroll
        for (int k = 0; k < BKD; k++) {
            float a0[4], a1[4], b0[4], b1[4];
            *(float4*)a0 = *(const float4*)&As[k][ty * 4];
            *(float4*)a1 = *(const float4*)&As[k][ty * 4 + 64];
            *(float4*)b0 = *(const float4*)&Bs[k][tx * 4];
            *(float4*)b1 = *(const float4*)&Bs[k][tx * 4 + 64];
#pragma unroll
            for (int i = 0; i < 4; i++) {
#pragma unroll
                for (int j = 0; j < 4; j++) {
                    acc[i][j]         += a0[i] * b0[j];
                    acc[i][j + 4]     += a0[i] * b1[j];
                    acc[i + 4][j]     += a1[i] * b0[j];
                    acc[i + 4][j + 4] += a1[i] * b1[j];
                }
            }
        }
        __syncthreads();
    }

    // ---- epilogue
#pragma unroll
    for (int i = 0; i < 8; i++) {
        int o = bm + ty * 4 + ((i < 4) ? i : (60 + i));   // i>=4: +64+(i-4)
        float bv = bias ? bias[o] : 0.f;
#pragma unroll
        for (int j = 0; j < 8; j++) {
            int n = bn + tx * 4 + ((j < 4) ? j : (60 + j));
            float v = acc[i][j] + bv;
            if (act == 1) v = 1.f / (1.f + expf(-v));
            C[(long long)o * Ndim + n] = v;
        }
    }
}

// ---------------------------------------------------------------------------
// Pooling: per (b,c) row of outpre -> avg and max over NPIX
// ---------------------------------------------------------------------------
__global__ __launch_bounds__(256)
void pool_kernel(const float* __restrict__ outp, float* __restrict__ pool)
{
    const int row = blockIdx.x;                 // b*CCH + c
    const float* p = outp + (long long)row * NPIX;
    const int tid = threadIdx.x;

    float s = 0.f, m = -3.402823466e38f;
    for (int i = tid; i < NPIX; i += 256) {
        float v = p[i];
        s += v;
        m = fmaxf(m, v);
    }
    __shared__ float ss[256], sm[256];
    ss[tid] = s; sm[tid] = m;
    __syncthreads();
    for (int off = 128; off > 0; off >>= 1) {
        if (tid < off) {
            ss[tid] += ss[tid + off];
            sm[tid]  = fmaxf(sm[tid], sm[tid + off]);
        }
        __syncthreads();
    }
    if (tid == 0) {
        pool[row]               = ss[0] * (1.f / NPIX);
        pool[BATCH * CCH + row] = sm[0];
    }
}

// ---------------------------------------------------------------------------
// CBAM gate: gate[b,c] = sigmoid( Wca2 @ (relu(Wca1@avg) + relu(Wca1@max)) )
// ---------------------------------------------------------------------------
__global__ __launch_bounds__(256)
void gate_kernel(const float* __restrict__ pool,
                 const float* __restrict__ Wca1,    // [R, C] row-major
                 const float* __restrict__ Wca2,    // [C, R] row-major
                 float* __restrict__ gate)
{
    const int b = blockIdx.x;
    const int tid = threadIdx.x;
    __shared__ float avg_s[CCH], max_s[CCH], h[RCH];

    for (int c = tid; c < CCH; c += 256) {
        avg_s[c] = pool[b * CCH + c];
        max_s[c] = pool[BATCH * CCH + b * CCH + c];
    }
    __syncthreads();

    for (int r = tid; r < RCH; r += 256) {
        float s1 = 0.f, s2 = 0.f;
        const float* wrow = Wca1 + (long long)r * CCH;
        for (int c = 0; c < CCH; c++) {
            s1 += wrow[c] * avg_s[c];
            s2 += wrow[c] * max_s[c];
        }
        h[r] = fmaxf(s1, 0.f) + fmaxf(s2, 0.f);
    }
    __syncthreads();

    for (int c = tid; c < CCH; c += 256) {
        float g = 0.f;
        const float* wrow = Wca2 + (long long)c * RCH;
#pragma unroll 8
        for (int r = 0; r < RCH; r++) g += wrow[r] * h[r];
        gate[b * CCH + c] = 1.f / (1.f + expf(-g));
    }
}

// ---------------------------------------------------------------------------
// Broadcast scale: out = outpre * gate[b,c]   (vectorized float4)
// ---------------------------------------------------------------------------
__global__ __launch_bounds__(256)
void scale_kernel(const float* __restrict__ outpre,
                  const float* __restrict__ gate,
                  float* __restrict__ out)
{
    long long i = (long long)blockIdx.x * 256 + threadIdx.x;      // float4 index
    // total float4 = BATCH*CCH*NPIX/4 = 4194304, launched exactly
    int row = (int)(i >> 10);                                     // /(NPIX/4)
    float g = gate[row];
    float4 v = ((const float4*)outpre)[i];
    v.x *= g; v.y *= g; v.z *= g; v.w *= g;
    ((float4*)out)[i] = v;
}

// ---------------------------------------------------------------------------
// Host launcher
// Input order (metadata.txt): x, x1, Wq, bq, Wk, bk, Wv, bv, Wca1, Wca2
// ---------------------------------------------------------------------------
extern "C" void kernel_launch(void* const* d_in, const int* in_sizes, int n_in,
                              void* d_out, int out_size)
{
    const float* x    = (const float*)d_in[0];
    const float* x1   = (const float*)d_in[1];
    const float* Wq   = (const float*)d_in[2];
    const float* bq   = (const float*)d_in[3];
    const float* Wk   = (const float*)d_in[4];
    const float* bk   = (const float*)d_in[5];
    const float* Wv   = (const float*)d_in[6];
    const float* bv   = (const float*)d_in[7];
    const float* Wca1 = (const float*)d_in[8];
    const float* Wca2 = (const float*)d_in[9];
    float* out = (float*)d_out;

    void *pQ, *pK, *pV, *pAtt, *pOutpre, *pPool, *pGate;
    cudaGetSymbolAddress(&pQ,   g_Q);
    cudaGetSymbolAddress(&pK,   g_K);
    cudaGetSymbolAddress(&pV,   g_V);
    cudaGetSymbolAddress(&pAtt, g_att);
    cudaGetSymbolAddress(&pOutpre, g_outpre);
    cudaGetSymbolAddress(&pPool, g_pool);
    cudaGetSymbolAddress(&pGate, g_gate);

    const long long sX  = (long long)CCH * NPIX;     // per-batch x / x1 / V / outpre stride
    const long long sQK = (long long)DCH * NPIX;     // per-batch Q / K stride
    const long long sAT = (long long)NPIX * NPIX;    // per-batch att stride

    dim3 thr(256);

    // 1) Q = Wq @ x + bq          [O=128, N=4096, K=1024] per batch
    sgemm_kernel<<<dim3(NPIX / TILE, DCH / TILE, BATCH), thr>>>(
        NPIX, CCH,
        Wq, (long long)CCH, 1LL, 0LL,
        x, sX,
        bq,
        (float*)pQ, sQK, 0);

    // 2) K = Wk @ x + bk
    sgemm_kernel<<<dim3(NPIX / TILE, DCH / TILE, BATCH), thr>>>(
        NPIX, CCH,
        Wk, (long long)CCH, 1LL, 0LL,
        x, sX,
        bk,
        (float*)pK, sQK, 0);

    // 3) V = Wv @ x1 + bv         [O=1024, N=4096, K=1024]
    sgemm_kernel<<<dim3(NPIX / TILE, CCH / TILE, BATCH), thr>>>(
        NPIX, CCH,
        Wv, (long long)CCH, 1LL, 0LL,
        x1, sX,
        bv,
        (float*)pV, sX, 0);

    // 4) att[m,n] = sigmoid( sum_d K[d,m] * Q[d,n] )   [O=4096, N=4096, K=128]
    //    A = g_K with sAo=1 (transposed access), B = g_Q
    sgemm_kernel<<<dim3(NPIX / TILE, NPIX / TILE, BATCH), thr>>>(
        NPIX, DCH,
        (const float*)pK, 1LL, (long long)NPIX, sQK,
        (const float*)pQ, sQK,
        nullptr,
        (float*)pAtt, sAT, 1);

    // 5) outpre[c,n] = sum_m V[c,m] * att[m,n]         [O=1024, N=4096, K=4096]
    sgemm_kernel<<<dim3(NPIX / TILE, CCH / TILE, BATCH), thr>>>(
        NPIX, NPIX,
        (const float*)pV, (long long)NPIX, 1LL, sX,
        (const float*)pAtt, sAT,
        nullptr,
        (float*)pOutpre, sX, 0);

    // 6) avg/max pooling per (b,c)
    pool_kernel<<<BATCH * CCH, thr>>>((const float*)pOutpre, (float*)pPool);

    // 7) CBAM MLP gate
    gate_kernel<<<BATCH, thr>>>((const float*)pPool, Wca1, Wca2, (float*)pGate);

    // 8) out = outpre * gate
    scale_kernel<<<(BATCH * (long long)CCH * NPIX / 4) / 256, thr>>>(
        (const float*)pOutpre, (const float*)pGate, out);
}

// round 6
// speedup vs baseline: 2.1024x; 2.1024x over previous
#include <cuda_runtime.h>
#include <cuda_bf16.h>
#include <math.h>

// Problem constants
#define BATCH 4
#define CCH   1024          // C
#define DCH   128           // D = C/8
#define RCH   64            // R = C/16
#define NPIX  4096          // H*W  (all GEMMs have N = 4096, hard-coded)

// ---------------------------------------------------------------------------
// Scratch (device globals: allocation-free per harness rules)
// ---------------------------------------------------------------------------
__device__ float g_Wqk[(size_t)2 * DCH * CCH];                   // concat [256,1024]
__device__ float g_bqk[2 * DCH];
__device__ float g_QK [(size_t)BATCH * 2 * DCH * NPIX];          // 16 MB: rows 0-127 Q, 128-255 K
__device__ float g_V  [(size_t)BATCH * CCH * NPIX];              // 64 MB
__device__ float g_att[(size_t)BATCH * NPIX * NPIX];             // 268 MB: att[b][m][n]
__device__ float g_outpre[(size_t)BATCH * CCH * NPIX];           // 64 MB
__device__ float g_pool[2 * BATCH * CCH];
__device__ float g_gate[BATCH * CCH];

#define TILE 128
#define BKD  16

// ---------------------------------------------------------------------------
// Specialized tiled SGEMM, N fixed at 4096.
//   C[o,n] = act( sum_k A(o,k) * B[k*4096 + n] + bias[o] )
// AK=true : A(o,k) = A[o*sAo + k]      (k contiguous)
// AK=false: A(o,k) = A[k*4096 + o]     (o contiguous; row length 4096)
// 128x128x16 tile, 256 thr, 8x8/thread, double-buffered SMEM + reg prefetch.
// All dims exact multiples -> no predication.
// ---------------------------------------------------------------------------
template<int KDIM, bool AK, bool BIASED, bool SIG>
__global__ __launch_bounds__(256, 2)
void gemm_t(const float* __restrict__ Aall, int sAo, long long sAb,
            const float* __restrict__ Ball, long long sBb,
            const float* __restrict__ bias,
            float* __restrict__ Call, long long sCb)
{
    __shared__ float As[2][BKD][TILE];
    __shared__ float Bs[2][BKD][TILE];

    const int bn = blockIdx.x * TILE;
    const int bm = blockIdx.y * TILE;
    const int b  = blockIdx.z;

    const float* A = Aall + (long long)b * sAb;
    const float* B = Ball + (long long)b * sBb;
    float*       C = Call + (long long)b * sCb;

    const int tid = threadIdx.x;
    const int tx  = tid & 15;
    const int ty  = tid >> 4;

    // --- load lane mapping
    // AK=true : row = bm + tid/2, 8 consecutive k starting at (tid&1)*8
    const int arow = tid >> 1;
    const int akq  = (tid & 1) * 8;
    // AK=false / B : k-row = tid/16, float4 col pair (ac, ac+64)
    const int lk = tid >> 4;
    const int lc = (tid & 15) * 4;

    const float* aT = A + (size_t)(bm + arow) * sAo + akq;     // AK=true
    const float* aF = A + (size_t)lk * 4096 + bm + lc;         // AK=false
    const float* bp = B + (size_t)lk * 4096 + bn + lc;

    float acc[8][8];
#pragma unroll
    for (int i = 0; i < 8; i++)
#pragma unroll
        for (int j = 0; j < 8; j++) acc[i][j] = 0.f;

    // ---- preload tile 0 into buffer 0
    if (AK) {
        float4 a0 = *(const float4*)(aT);
        float4 a1 = *(const float4*)(aT + 4);
#pragma unroll
        for (int j = 0; j < 4; j++) {
            As[0][akq + j][arow]     = ((const float*)&a0)[j];
            As[0][akq + 4 + j][arow] = ((const float*)&a1)[j];
        }
    } else {
        *(float4*)&As[0][lk][lc]      = *(const float4*)(aF);
        *(float4*)&As[0][lk][lc + 64] = *(const float4*)(aF + 64);
    }
    *(float4*)&Bs[0][lk][lc]      = *(const float4*)(bp);
    *(float4*)&Bs[0][lk][lc + 64] = *(const float4*)(bp + 64);
    __syncthreads();

    int buf = 0;
#pragma unroll 1
    for (int k0 = 0; k0 < KDIM; k0 += BKD) {
        const bool more = (k0 + BKD < KDIM);
        float4 pa0, pa1, pb0, pb1;
        if (more) {
            if (AK) {
                pa0 = *(const float4*)(aT + k0 + BKD);
                pa1 = *(const float4*)(aT + k0 + BKD + 4);
            } else {
                const float* an = aF + (size_t)(k0 + BKD) * 4096;
                pa0 = *(const float4*)(an);
                pa1 = *(const float4*)(an + 64);
            }
            const float* bnx = bp + (size_t)(k0 + BKD) * 4096;
            pb0 = *(const float4*)(bnx);
            pb1 = *(const float4*)(bnx + 64);
        }

#pragma unroll
        for (int k = 0; k < BKD; k++) {
            float ar[8], br[8];
            *(float4*)&ar[0] = *(const float4*)&As[buf][k][ty * 4];
            *(float4*)&ar[4] = *(const float4*)&As[buf][k][ty * 4 + 64];
            *(float4*)&br[0] = *(const float4*)&Bs[buf][k][tx * 4];
            *(float4*)&br[4] = *(const float4*)&Bs[buf][k][tx * 4 + 64];
#pragma unroll
            for (int i = 0; i < 8; i++)
#pragma unroll
                for (int j = 0; j < 8; j++)
                    acc[i][j] += ar[i] * br[j];
        }

        if (more) {
            const int nb = buf ^ 1;
            if (AK) {
#pragma unroll
                for (int j = 0; j < 4; j++) {
                    As[nb][akq + j][arow]     = ((const float*)&pa0)[j];
                    As[nb][akq + 4 + j][arow] = ((const float*)&pa1)[j];
                }
            } else {
                *(float4*)&As[nb][lk][lc]      = pa0;
                *(float4*)&As[nb][lk][lc + 64] = pa1;
            }
            *(float4*)&Bs[nb][lk][lc]      = pb0;
            *(float4*)&Bs[nb][lk][lc + 64] = pb1;
        }
        __syncthreads();
        buf ^= 1;
    }

    // ---- epilogue (vectorized)
#pragma unroll
    for (int i = 0; i < 8; i++) {
        const int o = bm + ty * 4 + ((i < 4) ? i : (60 + i));
        const float bv = BIASED ? bias[o] : 0.f;
        float* crow = C + (size_t)o * 4096 + bn + tx * 4;
        float4 v0, v1;
        float* p0 = (float*)&v0;
        float* p1 = (float*)&v1;
#pragma unroll
        for (int j = 0; j < 4; j++) {
            float a = acc[i][j] + bv;
            float c = acc[i][j + 4] + bv;
            if (SIG) {
                a = __fdividef(1.f, 1.f + __expf(-a));
                c = __fdividef(1.f, 1.f + __expf(-c));
            }
            p0[j] = a; p1[j] = c;
        }
        *(float4*)(crow)      = v0;
        *(float4*)(crow + 64) = v1;
    }
}

// ---------------------------------------------------------------------------
// Concat Wq/Wk (and biases) so Q,K run as one GEMM with O=256
// ---------------------------------------------------------------------------
__global__ __launch_bounds__(256)
void concat_qk(const float* __restrict__ Wq, const float* __restrict__ bq,
               const float* __restrict__ Wk, const float* __restrict__ bk,
               float* __restrict__ Wqk, float* __restrict__ bqk)
{
    int i = blockIdx.x * 256 + threadIdx.x;        // 0 .. 262143
    Wqk[i] = (i < DCH * CCH) ? Wq[i] : Wk[i - DCH * CCH];
    if (i < 2 * DCH)
        bqk[i] = (i < DCH) ? bq[i] : bk[i - DCH];
}

// ---------------------------------------------------------------------------
// Pooling: per (b,c) row of outpre -> avg and max over NPIX
// ---------------------------------------------------------------------------
__global__ __launch_bounds__(256)
void pool_kernel(const float* __restrict__ outp, float* __restrict__ pool)
{
    const int row = blockIdx.x;
    const float4* p = (const float4*)(outp + (size_t)row * NPIX);
    const int tid = threadIdx.x;

    float s = 0.f, m = -3.402823466e38f;
    for (int i = tid; i < NPIX / 4; i += 256) {
        float4 v = p[i];
        s += v.x + v.y + v.z + v.w;
        m = fmaxf(m, fmaxf(fmaxf(v.x, v.y), fmaxf(v.z, v.w)));
    }
    __shared__ float ss[256], sm[256];
    ss[tid] = s; sm[tid] = m;
    __syncthreads();
    for (int off = 128; off > 0; off >>= 1) {
        if (tid < off) {
            ss[tid] += ss[tid + off];
            sm[tid]  = fmaxf(sm[tid], sm[tid + off]);
        }
        __syncthreads();
    }
    if (tid == 0) {
        pool[row]               = ss[0] * (1.f / NPIX);
        pool[BATCH * CCH + row] = sm[0];
    }
}

// ---------------------------------------------------------------------------
// CBAM gate
// ---------------------------------------------------------------------------
__global__ __launch_bounds__(256)
void gate_kernel(const float* __restrict__ pool,
                 const float* __restrict__ Wca1,    // [R, C]
                 const float* __restrict__ Wca2,    // [C, R]
                 float* __restrict__ gate)
{
    const int b = blockIdx.x;
    const int tid = threadIdx.x;
    __shared__ float avg_s[CCH], max_s[CCH], h[RCH];

    for (int c = tid; c < CCH; c += 256) {
        avg_s[c] = pool[b * CCH + c];
        max_s[c] = pool[BATCH * CCH + b * CCH + c];
    }
    __syncthreads();

    for (int r = tid; r < RCH; r += 256) {
        float s1 = 0.f, s2 = 0.f;
        const float* wrow = Wca1 + (size_t)r * CCH;
        for (int c = 0; c < CCH; c++) {
            s1 += wrow[c] * avg_s[c];
            s2 += wrow[c] * max_s[c];
        }
        h[r] = fmaxf(s1, 0.f) + fmaxf(s2, 0.f);
    }
    __syncthreads();

    for (int c = tid; c < CCH; c += 256) {
        float g = 0.f;
        const float* wrow = Wca2 + (size_t)c * RCH;
#pragma unroll 8
        for (int r = 0; r < RCH; r++) g += wrow[r] * h[r];
        gate[b * CCH + c] = 1.f / (1.f + expf(-g));
    }
}

// ---------------------------------------------------------------------------
// Broadcast scale: out = outpre * gate[b,c]
// ---------------------------------------------------------------------------
__global__ __launch_bounds__(256)
void scale_kernel(const float* __restrict__ outpre,
                  const float* __restrict__ gate,
                  float* __restrict__ out)
{
    size_t i = (size_t)blockIdx.x * 256 + threadIdx.x;   // float4 index
    int row = (int)(i >> 10);                            // /(NPIX/4)
    float g = gate[row];
    float4 v = ((const float4*)outpre)[i];
    v.x *= g; v.y *= g; v.z *= g; v.w *= g;
    ((float4*)out)[i] = v;
}

// ---------------------------------------------------------------------------
// Host launcher
// Input order: x, x1, Wq, bq, Wk, bk, Wv, bv, Wca1, Wca2
// ---------------------------------------------------------------------------
extern "C" void kernel_launch(void* const* d_in, const int* in_sizes, int n_in,
                              void* d_out, int out_size)
{
    const float* x    = (const float*)d_in[0];
    const float* x1   = (const float*)d_in[1];
    const float* Wq   = (const float*)d_in[2];
    const float* bq   = (const float*)d_in[3];
    const float* Wk   = (const float*)d_in[4];
    const float* bk   = (const float*)d_in[5];
    const float* Wv   = (const float*)d_in[6];
    const float* bv   = (const float*)d_in[7];
    const float* Wca1 = (const float*)d_in[8];
    const float* Wca2 = (const float*)d_in[9];
    float* out = (float*)d_out;

    void *pWqk, *pbqk, *pQK, *pV, *pAtt, *pOutpre, *pPool, *pGate;
    cudaGetSymbolAddress(&pWqk, g_Wqk);
    cudaGetSymbolAddress(&pbqk, g_bqk);
    cudaGetSymbolAddress(&pQK,  g_QK);
    cudaGetSymbolAddress(&pV,   g_V);
    cudaGetSymbolAddress(&pAtt, g_att);
    cudaGetSymbolAddress(&pOutpre, g_outpre);
    cudaGetSymbolAddress(&pPool, g_pool);
    cudaGetSymbolAddress(&pGate, g_gate);

    const long long sX   = (long long)CCH * NPIX;       // x / x1 / V / outpre batch stride
    const long long sQKb = (long long)2 * DCH * NPIX;   // QK batch stride
    const long long sAT  = (long long)NPIX * NPIX;      // att batch stride

    dim3 thr(256);

    // 0) concat Wq|Wk
    concat_qk<<<(2 * DCH * CCH) / 256, thr>>>(Wq, bq, Wk, bk, (float*)pWqk, (float*)pbqk);

    // 1) [Q;K] = Wqk @ x + bqk      O=256, K=1024
    gemm_t<CCH, true, true, false><<<dim3(NPIX / TILE, 2 * DCH / TILE, BATCH), thr>>>(
        (const float*)pWqk, CCH, 0LL, x, sX, (const float*)pbqk, (float*)pQK, sQKb);

    // 2) V = Wv @ x1 + bv           O=1024, K=1024
    gemm_t<CCH, true, true, false><<<dim3(NPIX / TILE, CCH / TILE, BATCH), thr>>>(
        Wv, CCH, 0LL, x1, sX, bv, (float*)pV, sX);

    // 3) att[m,n] = sigmoid( sum_d K[d,m]*Q[d,n] )   O=4096, K=128
    //    A = K part of QK (AK=false), B = Q part
    gemm_t<DCH, false, false, true><<<dim3(NPIX / TILE, NPIX / TILE, BATCH), thr>>>(
        (const float*)pQK + (size_t)DCH * NPIX, 0, sQKb,
        (const float*)pQK, sQKb, nullptr, (float*)pAtt, sAT);

    // 4) outpre[c,n] = sum_m V[c,m]*att[m,n]         O=1024, K=4096
    gemm_t<NPIX, true, false, false><<<dim3(NPIX / TILE, CCH / TILE, BATCH), thr>>>(
        (const float*)pV, NPIX, sX, (const float*)pAtt, sAT, nullptr, (float*)pOutpre, sX);

    // 5) pooling, gate, scale
    pool_kernel<<<BATCH * CCH, thr>>>((const float*)pOutpre, (float*)pPool);
    gate_kernel<<<BATCH, thr>>>((const float*)pPool, Wca1, Wca2, (float*)pGate);
    scale_kernel<<<(int)(((size_t)BATCH * CCH * NPIX / 4) / 256), thr>>>(
        (const float*)pOutpre, (const float*)pGate, out);
}

// round 8
// speedup vs baseline: 4.8865x; 2.3242x over previous
#include <cuda_runtime.h>
#include <cuda_bf16.h>
#include <math.h>
#include <stdint.h>

#define BATCH 4
#define CCH   1024
#define DCH   128
#define RCH   64
#define NPIX  4096

// ===========================================================================
// Scratch (device globals — allocation-free)
// ===========================================================================
__device__ __nv_bfloat16 g_xThi [(size_t)BATCH * NPIX * CCH];   // x^T  [b][n][c]
__device__ __nv_bfloat16 g_xTlo [(size_t)BATCH * NPIX * CCH];
__device__ __nv_bfloat16 g_x1Thi[(size_t)BATCH * NPIX * CCH];   // x1^T [b][n][c]
__device__ __nv_bfloat16 g_x1Tlo[(size_t)BATCH * NPIX * CCH];
__device__ __nv_bfloat16 g_Wqkhi[(size_t)2 * DCH * CCH];        // [256][1024]
__device__ __nv_bfloat16 g_Wqklo[(size_t)2 * DCH * CCH];
__device__ float         g_bqk[2 * DCH];
__device__ __nv_bfloat16 g_Wvhi[(size_t)CCH * CCH];
__device__ __nv_bfloat16 g_Wvlo[(size_t)CCH * CCH];
__device__ __nv_bfloat16 g_QKThi[(size_t)BATCH * NPIX * 2 * DCH]; // [b][n][256] (Q 0-127, K 128-255)
__device__ __nv_bfloat16 g_QKTlo[(size_t)BATCH * NPIX * 2 * DCH];
__device__ __nv_bfloat16 g_Vhi [(size_t)BATCH * CCH * NPIX];    // [b][c][m]
__device__ __nv_bfloat16 g_Vlo [(size_t)BATCH * CCH * NPIX];
__device__ __nv_bfloat16 g_atthi[(size_t)BATCH * NPIX * NPIX];  // [b][n][m]
__device__ __nv_bfloat16 g_attlo[(size_t)BATCH * NPIX * NPIX];
__device__ float g_outpre[(size_t)BATCH * CCH * NPIX];          // [b][c][n] fp32
__device__ float g_pool[2 * BATCH * CCH];
__device__ float g_gate[BATCH * CCH];

// ===========================================================================
// Baseline-PTX helpers (NO 'a'-suffix features: mma.sync / ldmatrix / cp.async)
// ===========================================================================
__device__ __forceinline__ uint32_t smem_u32(const void* p) {
    uint32_t a;
    asm("{ .reg .u64 t; cvta.to.shared.u64 t, %1; cvt.u32.u64 %0, t; }" : "=r"(a) : "l"(p));
    return a;
}
#define SWZ128(x) ((x) ^ (((x) >> 3) & 0x70))

__device__ __forceinline__ void cpa16(uint32_t s, const void* g) {
    asm volatile("cp.async.cg.shared.global [%0], [%1], 16;" :: "r"(s), "l"(g));
}
#define CP_COMMIT() asm volatile("cp.async.commit_group;" ::: "memory")
#define CP_WAIT0()  asm volatile("cp.async.wait_group 0;"  ::: "memory")

__device__ __forceinline__ void ldm4(uint32_t* r, uint32_t a) {
    asm volatile("ldmatrix.sync.aligned.m8n8.x4.shared.b16 {%0,%1,%2,%3}, [%4];"
        : "=r"(r[0]), "=r"(r[1]), "=r"(r[2]), "=r"(r[3]) : "r"(a));
}
__device__ __forceinline__ void mma16816(float* d, const uint32_t* a, const uint32_t* b) {
    asm volatile("mma.sync.aligned.m16n8k16.row.col.f32.bf16.bf16.f32 "
        "{%0,%1,%2,%3}, {%4,%5,%6,%7}, {%8,%9}, {%0,%1,%2,%3};"
        : "+f"(d[0]), "+f"(d[1]), "+f"(d[2]), "+f"(d[3])
        : "r"(a[0]), "r"(a[1]), "r"(a[2]), "r"(a[3]), "r"(b[0]), "r"(b[1]));
}

// ===========================================================================
// SMEM: 2 stages x (Ahi|Alo|Bhi|Blo), each 128 rows x 128B (KC=64 bf16), SW128.
// Epilogue reuses the region as a 128x132 fp32 staging tile.
// ===========================================================================
#define KC 64
#define STAGE_BYTES (4 * 16384)
#define OFF_AH(s) ((s) * STAGE_BYTES + 0)
#define OFF_AL(s) ((s) * STAGE_BYTES + 16384)
#define OFF_BH(s) ((s) * STAGE_BYTES + 32768)
#define OFF_BL(s) ((s) * STAGE_BYTES + 49152)
#define SMEM_BYTES (2 * STAGE_BYTES)     // 131072

__device__ __forceinline__ void ld_stage(uint32_t sb, int s,
    const __nv_bfloat16* __restrict__ Ahi, const __nv_bfloat16* __restrict__ Alo, int pitchA,
    const __nv_bfloat16* __restrict__ Bhi, const __nv_bfloat16* __restrict__ Blo, int pitchB,
    int k0, int tid)
{
#pragma unroll
    for (int t = 0; t < 4; t++) {
        int i = tid + t * 256;                  // 0..1023
        int row = i >> 3;
        int ch  = (i & 7) * 16;                 // byte offset within 128B row
        uint32_t so = SWZ128((uint32_t)(row * 128 + ch));
        cpa16(sb + OFF_AH(s) + so, (const char*)(Ahi + (size_t)row * pitchA + k0) + ch);
        cpa16(sb + OFF_AL(s) + so, (const char*)(Alo + (size_t)row * pitchA + k0) + ch);
        cpa16(sb + OFF_BH(s) + so, (const char*)(Bhi + (size_t)row * pitchB + k0) + ch);
        cpa16(sb + OFF_BL(s) + so, (const char*)(Blo + (size_t)row * pitchB + k0) + ch);
    }
}

// EPI: 0 = bias per col + split store   1 = bias per row + split store
//      2 = sigmoid + split store        3 = plain fp32 store
// SWAP: blockIdx.x indexes M (for L2-friendly rasterization on the bmm)
template<int KDIM, int EPI, bool SWAP>
__global__ __launch_bounds__(256, 1)
void mma_gemm(const __nv_bfloat16* __restrict__ Ahi, const __nv_bfloat16* __restrict__ Alo,
              int pitchA, long long sAb,
              const __nv_bfloat16* __restrict__ Bhi, const __nv_bfloat16* __restrict__ Blo,
              int pitchB, long long sBb,
              const float* __restrict__ bias,
              void* __restrict__ Cout, __nv_bfloat16* __restrict__ Clo,
              int pitchC, long long sCb)
{
    extern __shared__ char smem[];
    const uint32_t sb = smem_u32(smem);
    const int tid = threadIdx.x;
    const int bm = (SWAP ? blockIdx.x : blockIdx.y) * 128;
    const int bn = (SWAP ? blockIdx.y : blockIdx.x) * 128;
    const int b  = blockIdx.z;

    Ahi += (size_t)b * sAb + (size_t)bm * pitchA;
    Alo += (size_t)b * sAb + (size_t)bm * pitchA;
    Bhi += (size_t)b * sBb + (size_t)bn * pitchB;
    Blo += (size_t)b * sBb + (size_t)bn * pitchB;

    constexpr int NC = KDIM / KC;

    // warp decomposition: 8 warps = 4(M) x 2(N); warp tile 32(M) x 64(N)
    const int w  = tid >> 5, l = tid & 31;
    const int wm = (w & 3) * 32;
    const int wn = (w >> 2) * 64;

    // lane constants for ldmatrix addressing
    const int a_row   = l & 15;             // row within m16 tile
    const int a_kb    = (l >> 4) * 16;      // k-half byte offset
    const int b_noff  = ((l >> 4) & 1) * 8 + (l & 7);  // row within n16 pair
    const int b_kb    = ((l >> 3) & 1) * 16;           // k-half byte offset

    float acc[2][8][4];
#pragma unroll
    for (int i = 0; i < 2; i++)
#pragma unroll
        for (int j = 0; j < 8; j++)
#pragma unroll
            for (int q = 0; q < 4; q++) acc[i][j][q] = 0.f;

    ld_stage(sb, 0, Ahi, Alo, pitchA, Bhi, Blo, pitchB, 0, tid);
    CP_COMMIT();

    int buf = 0;
#pragma unroll 1
    for (int c = 0; c < NC; c++) {
        CP_WAIT0();
        __syncthreads();
        if (c + 1 < NC) {
            ld_stage(sb, buf ^ 1, Ahi, Alo, pitchA, Bhi, Blo, pitchB, (c + 1) * KC, tid);
            CP_COMMIT();
        }
        const uint32_t bAH = sb + OFF_AH(buf), bAL = sb + OFF_AL(buf);
        const uint32_t bBH = sb + OFF_BH(buf), bBL = sb + OFF_BL(buf);

#pragma unroll
        for (int ks = 0; ks < 4; ks++) {
            const int kb = ks * 32;
            uint32_t ah[2][4], al[2][4];
#pragma unroll
            for (int mt = 0; mt < 2; mt++) {
                uint32_t off = SWZ128((uint32_t)((wm + mt * 16 + a_row) * 128 + kb + a_kb));
                ldm4(ah[mt], bAH + off);
                ldm4(al[mt], bAL + off);
            }
            uint32_t bh[8][2], bl[8][2];
#pragma unroll
            for (int p = 0; p < 4; p++) {
                uint32_t off = SWZ128((uint32_t)((wn + p * 16 + b_noff) * 128 + kb + b_kb));
                uint32_t r[4];
                ldm4(r, bBH + off);
                bh[2 * p][0] = r[0]; bh[2 * p][1] = r[1];
                bh[2 * p + 1][0] = r[2]; bh[2 * p + 1][1] = r[3];
                ldm4(r, bBL + off);
                bl[2 * p][0] = r[0]; bl[2 * p][1] = r[1];
                bl[2 * p + 1][0] = r[2]; bl[2 * p + 1][1] = r[3];
            }
#pragma unroll
            for (int mt = 0; mt < 2; mt++)
#pragma unroll
                for (int nt = 0; nt < 8; nt++) {
                    mma16816(acc[mt][nt], ah[mt], bh[nt]);   // hi*hi
                    mma16816(acc[mt][nt], ah[mt], bl[nt]);   // hi*lo
                    mma16816(acc[mt][nt], al[mt], bh[nt]);   // lo*hi
                }
        }
        buf ^= 1;
    }
    __syncthreads();   // done reading operand SMEM; reuse as staging

    // ---- epilogue: regs -> SMEM stage (fp32, pitch 132) -> coalesced GMEM
    float* stage = (float*)smem;
    {
        const int qr = l >> 2, qc = (l & 3) * 2;
#pragma unroll
        for (int mt = 0; mt < 2; mt++)
#pragma unroll
            for (int nt = 0; nt < 8; nt++) {
                int r0 = wm + mt * 16 + qr;
                int c0 = wn + nt * 8 + qc;
                *(float2*)&stage[(size_t)r0 * 132 + c0] =
                    make_float2(acc[mt][nt][0], acc[mt][nt][1]);
                *(float2*)&stage[(size_t)(r0 + 8) * 132 + c0] =
                    make_float2(acc[mt][nt][2], acc[mt][nt][3]);
            }
    }
    __syncthreads();

    for (int g = tid; g < 2048; g += 256) {
        int row = g >> 4;
        int lc  = (g & 15) * 8;
        const float* st = stage + (size_t)row * 132 + lc;
        int orow = bm + row;
        int ncol = bn + lc;
        float v[8];
#pragma unroll
        for (int j = 0; j < 8; j++) {
            float x = st[j];
            if (EPI == 0) x += bias[ncol + j];
            if (EPI == 1) x += bias[orow];
            if (EPI == 2) x = __fdividef(1.f, 1.f + __expf(-x));
            v[j] = x;
        }
        if (EPI == 3) {
            float* dst = (float*)Cout + (size_t)b * sCb + (size_t)orow * pitchC + ncol;
            *(float4*)dst       = make_float4(v[0], v[1], v[2], v[3]);
            *(float4*)(dst + 4) = make_float4(v[4], v[5], v[6], v[7]);
        } else {
            uint16_t hb[8], lb[8];
#pragma unroll
            for (int j = 0; j < 8; j++) {
                __nv_bfloat16 h = __float2bfloat16(v[j]);
                __nv_bfloat16 lo = __float2bfloat16(v[j] - __bfloat162float(h));
                hb[j] = *(uint16_t*)&h;
                lb[j] = *(uint16_t*)&lo;
            }
            __nv_bfloat16* dh = (__nv_bfloat16*)Cout + (size_t)b * sCb + (size_t)orow * pitchC + ncol;
            __nv_bfloat16* dl = Clo                + (size_t)b * sCb + (size_t)orow * pitchC + ncol;
            *(uint4*)dh = *(uint4*)hb;
            *(uint4*)dl = *(uint4*)lb;
        }
    }
}

// ===========================================================================
// Prep kernels
// ===========================================================================
__global__ __launch_bounds__(256)
void transpose_split(const float* __restrict__ src,
                     __nv_bfloat16* __restrict__ dhi, __nv_bfloat16* __restrict__ dlo)
{
    __shared__ float t[32][33];
    const int b = blockIdx.z;
    const int n0 = blockIdx.x * 32, c0 = blockIdx.y * 32;
    const float* s = src + (size_t)b * CCH * NPIX;
    const int tx = threadIdx.x, ty = threadIdx.y;      // (32, 8)
#pragma unroll
    for (int j = 0; j < 32; j += 8)
        t[ty + j][tx] = s[(size_t)(c0 + ty + j) * NPIX + n0 + tx];
    __syncthreads();
    const size_t base = (size_t)b * NPIX * CCH;
#pragma unroll
    for (int j = 0; j < 32; j += 8) {
        float v = t[tx][ty + j];
        __nv_bfloat16 h = __float2bfloat16(v);
        __nv_bfloat16 l = __float2bfloat16(v - __bfloat162float(h));
        size_t off = base + (size_t)(n0 + ty + j) * CCH + c0 + tx;
        dhi[off] = h; dlo[off] = l;
    }
}

__global__ __launch_bounds__(256)
void prep_wqk(const float* __restrict__ Wq, const float* __restrict__ bq,
              const float* __restrict__ Wk, const float* __restrict__ bk,
              __nv_bfloat16* __restrict__ whi, __nv_bfloat16* __restrict__ wlo,
              float* __restrict__ bqk)
{
    int i = blockIdx.x * 256 + threadIdx.x;
    float v = (i < DCH * CCH) ? Wq[i] : Wk[i - DCH * CCH];
    __nv_bfloat16 h = __float2bfloat16(v);
    whi[i] = h; wlo[i] = __float2bfloat16(v - __bfloat162float(h));
    if (i < 2 * DCH) bqk[i] = (i < DCH) ? bq[i] : bk[i - DCH];
}

__global__ __launch_bounds__(256)
void prep_wv(const float* __restrict__ Wv,
             __nv_bfloat16* __restrict__ whi, __nv_bfloat16* __restrict__ wlo)
{
    int i = blockIdx.x * 256 + threadIdx.x;
    float v = Wv[i];
    __nv_bfloat16 h = __float2bfloat16(v);
    whi[i] = h; wlo[i] = __float2bfloat16(v - __bfloat162float(h));
}

// ===========================================================================
// Pool / gate / scale
// ===========================================================================
__global__ __launch_bounds__(256)
void pool_kernel(const float* __restrict__ outp, float* __restrict__ pool)
{
    const int row = blockIdx.x;
    const float4* p = (const float4*)(outp + (size_t)row * NPIX);
    const int tid = threadIdx.x;
    float s = 0.f, m = -3.402823466e38f;
    for (int i = tid; i < NPIX / 4; i += 256) {
        float4 v = p[i];
        s += v.x + v.y + v.z + v.w;
        m = fmaxf(m, fmaxf(fmaxf(v.x, v.y), fmaxf(v.z, v.w)));
    }
    __shared__ float ss[256], sm[256];
    ss[tid] = s; sm[tid] = m;
    __syncthreads();
    for (int off = 128; off > 0; off >>= 1) {
        if (tid < off) { ss[tid] += ss[tid + off]; sm[tid] = fmaxf(sm[tid], sm[tid + off]); }
        __syncthreads();
    }
    if (tid == 0) {
        pool[row]               = ss[0] * (1.f / NPIX);
        pool[BATCH * CCH + row] = sm[0];
    }
}

__global__ __launch_bounds__(256)
void gate_kernel(const float* __restrict__ pool,
                 const float* __restrict__ Wca1, const float* __restrict__ Wca2,
                 float* __restrict__ gate)
{
    const int b = blockIdx.x;
    const int tid = threadIdx.x;
    __shared__ float avg_s[CCH], max_s[CCH], h[RCH];
    for (int c = tid; c < CCH; c += 256) {
        avg_s[c] = pool[b * CCH + c];
        max_s[c] = pool[BATCH * CCH + b * CCH + c];
    }
    __syncthreads();
    for (int r = tid; r < RCH; r += 256) {
        float s1 = 0.f, s2 = 0.f;
        const float* w = Wca1 + (size_t)r * CCH;
        for (int c = 0; c < CCH; c++) { s1 += w[c] * avg_s[c]; s2 += w[c] * max_s[c]; }
        h[r] = fmaxf(s1, 0.f) + fmaxf(s2, 0.f);
    }
    __syncthreads();
    for (int c = tid; c < CCH; c += 256) {
        float g = 0.f;
        const float* w = Wca2 + (size_t)c * RCH;
#pragma unroll 8
        for (int r = 0; r < RCH; r++) g += w[r] * h[r];
        gate[b * CCH + c] = 1.f / (1.f + expf(-g));
    }
}

__global__ __launch_bounds__(256)
void scale_kernel(const float* __restrict__ outpre, const float* __restrict__ gate,
                  float* __restrict__ out)
{
    size_t i = (size_t)blockIdx.x * 256 + threadIdx.x;
    int row = (int)(i >> 10);
    float g = gate[row];
    float4 v = ((const float4*)outpre)[i];
    v.x *= g; v.y *= g; v.z *= g; v.w *= g;
    ((float4*)out)[i] = v;
}

// ===========================================================================
// Host launcher.  Inputs: x, x1, Wq, bq, Wk, bk, Wv, bv, Wca1, Wca2
// ===========================================================================
extern "C" void kernel_launch(void* const* d_in, const int* in_sizes, int n_in,
                              void* d_out, int out_size)
{
    const float* x    = (const float*)d_in[0];
    const float* x1   = (const float*)d_in[1];
    const float* Wq   = (const float*)d_in[2];
    const float* bq   = (const float*)d_in[3];
    const float* Wk   = (const float*)d_in[4];
    const float* bk   = (const float*)d_in[5];
    const float* Wv   = (const float*)d_in[6];
    const float* bv   = (const float*)d_in[7];
    const float* Wca1 = (const float*)d_in[8];
    const float* Wca2 = (const float*)d_in[9];
    float* out = (float*)d_out;

    static bool attr_done = false;
    if (!attr_done) {
        cudaFuncSetAttribute(mma_gemm<1024, 0, false>, cudaFuncAttributeMaxDynamicSharedMemorySize, SMEM_BYTES);
        cudaFuncSetAttribute(mma_gemm<1024, 1, false>, cudaFuncAttributeMaxDynamicSharedMemorySize, SMEM_BYTES);
        cudaFuncSetAttribute(mma_gemm<128,  2, false>, cudaFuncAttributeMaxDynamicSharedMemorySize, SMEM_BYTES);
        cudaFuncSetAttribute(mma_gemm<4096, 3, true >, cudaFuncAttributeMaxDynamicSharedMemorySize, SMEM_BYTES);
        attr_done = true;
    }

    void *pxh,*pxl,*p1h,*p1l,*pwh,*pwl,*pbqk,*pvh,*pvl,*pqh,*pql,*pVh,*pVl,*pah,*pal,*pop,*ppool,*pgate;
    cudaGetSymbolAddress(&pxh, g_xThi);  cudaGetSymbolAddress(&pxl, g_xTlo);
    cudaGetSymbolAddress(&p1h, g_x1Thi); cudaGetSymbolAddress(&p1l, g_x1Tlo);
    cudaGetSymbolAddress(&pwh, g_Wqkhi); cudaGetSymbolAddress(&pwl, g_Wqklo);
    cudaGetSymbolAddress(&pbqk, g_bqk);
    cudaGetSymbolAddress(&pvh, g_Wvhi);  cudaGetSymbolAddress(&pvl, g_Wvlo);
    cudaGetSymbolAddress(&pqh, g_QKThi); cudaGetSymbolAddress(&pql, g_QKTlo);
    cudaGetSymbolAddress(&pVh, g_Vhi);   cudaGetSymbolAddress(&pVl, g_Vlo);
    cudaGetSymbolAddress(&pah, g_atthi); cudaGetSymbolAddress(&pal, g_attlo);
    cudaGetSymbolAddress(&pop, g_outpre);
    cudaGetSymbolAddress(&ppool, g_pool); cudaGetSymbolAddress(&pgate, g_gate);

    dim3 thr(256);
    dim3 tthr(32, 8);

    // prep: transpose + bf16 hi/lo split
    transpose_split<<<dim3(NPIX / 32, CCH / 32, BATCH), tthr>>>(x,  (__nv_bfloat16*)pxh, (__nv_bfloat16*)pxl);
    transpose_split<<<dim3(NPIX / 32, CCH / 32, BATCH), tthr>>>(x1, (__nv_bfloat16*)p1h, (__nv_bfloat16*)p1l);
    prep_wqk<<<(2 * DCH * CCH) / 256, thr>>>(Wq, bq, Wk, bk,
        (__nv_bfloat16*)pwh, (__nv_bfloat16*)pwl, (float*)pbqk);
    prep_wv<<<(CCH * CCH) / 256, thr>>>(Wv, (__nv_bfloat16*)pvh, (__nv_bfloat16*)pvl);

    const long long sXT = (long long)NPIX * CCH;
    const long long sQK = (long long)NPIX * 2 * DCH;
    const long long sV  = (long long)CCH * NPIX;
    const long long sAT = (long long)NPIX * NPIX;

    // 1) QKT[n][0:256] = xT @ Wqk^T + bqk   (M=4096, N=256, K=1024)
    mma_gemm<1024, 0, false><<<dim3(2, 32, BATCH), thr, SMEM_BYTES>>>(
        (const __nv_bfloat16*)pxh, (const __nv_bfloat16*)pxl, CCH, sXT,
        (const __nv_bfloat16*)pwh, (const __nv_bfloat16*)pwl, CCH, 0LL,
        (const float*)pbqk, pqh, (__nv_bfloat16*)pql, 2 * DCH, sQK);

    // 2) V[c][m] = Wv @ x1 + bv             (M=1024, N=4096, K=1024)
    mma_gemm<1024, 1, false><<<dim3(32, 8, BATCH), thr, SMEM_BYTES>>>(
        (const __nv_bfloat16*)pvh, (const __nv_bfloat16*)pvl, CCH, 0LL,
        (const __nv_bfloat16*)p1h, (const __nv_bfloat16*)p1l, CCH, sXT,
        bv, pVh, (__nv_bfloat16*)pVl, NPIX, sV);

    // 3) att[n][m] = sigmoid(Q_n . K_m)     (M=4096, N=4096, K=128)
    mma_gemm<128, 2, false><<<dim3(32, 32, BATCH), thr, SMEM_BYTES>>>(
        (const __nv_bfloat16*)pqh,       (const __nv_bfloat16*)pql,       2 * DCH, sQK,
        (const __nv_bfloat16*)pqh + DCH, (const __nv_bfloat16*)pql + DCH, 2 * DCH, sQK,
        nullptr, pah, (__nv_bfloat16*)pal, NPIX, sAT);

    // 4) outpre[c][n] = sum_m V[c][m] att[n][m]  (M=1024, N=4096, K=4096)
    //    SWAP rasterization: x = M-blocks so att tiles are shared across
    //    consecutive CTAs and V (32MB) stays L2-resident.
    mma_gemm<4096, 3, true><<<dim3(8, 32, BATCH), thr, SMEM_BYTES>>>(
        (const __nv_bfloat16*)pVh, (const __nv_bfloat16*)pVl, NPIX, sV,
        (const __nv_bfloat16*)pah, (const __nv_bfloat16*)pal, NPIX, sAT,
        nullptr, pop, nullptr, NPIX, sV);

    // 5) tail
    pool_kernel<<<BATCH * CCH, thr>>>((const float*)pop, (float*)ppool);
    gate_kernel<<<BATCH, thr>>>((const float*)ppool, Wca1, Wca2, (float*)pgate);
    scale_kernel<<<(int)(((size_t)BATCH * CCH * NPIX / 4) / 256), thr>>>(
        (const float*)pop, (const float*)pgate, out);
}

// round 9
// speedup vs baseline: 4.8868x; 1.0001x over previous
#include <cuda_runtime.h>
#include <cuda_bf16.h>
#include <math.h>
#include <stdint.h>

#define BATCH 4
#define CCH   1024
#define DCH   128
#define RCH   64
#define NPIX  4096

// ===========================================================================
// Scratch (device globals — allocation-free)
// ===========================================================================
__device__ __nv_bfloat16 g_xThi [(size_t)BATCH * NPIX * CCH];   // x^T  [b][n][c]
__device__ __nv_bfloat16 g_xTlo [(size_t)BATCH * NPIX * CCH];
__device__ __nv_bfloat16 g_x1Thi[(size_t)BATCH * NPIX * CCH];   // x1^T [b][n][c]
__device__ __nv_bfloat16 g_x1Tlo[(size_t)BATCH * NPIX * CCH];
__device__ __nv_bfloat16 g_Wqkhi[(size_t)2 * DCH * CCH];        // [256][1024]
__device__ __nv_bfloat16 g_Wqklo[(size_t)2 * DCH * CCH];
__device__ float         g_bqk[2 * DCH];
__device__ __nv_bfloat16 g_Wvhi[(size_t)CCH * CCH];
__device__ __nv_bfloat16 g_Wvlo[(size_t)CCH * CCH];
__device__ __nv_bfloat16 g_QKThi[(size_t)BATCH * NPIX * 2 * DCH]; // [b][n][256] (Q 0-127, K 128-255)
__device__ __nv_bfloat16 g_QKTlo[(size_t)BATCH * NPIX * 2 * DCH];
__device__ __nv_bfloat16 g_Vhi [(size_t)BATCH * CCH * NPIX];    // [b][c][m]
__device__ __nv_bfloat16 g_Vlo [(size_t)BATCH * CCH * NPIX];
__device__ __nv_bfloat16 g_atthi[(size_t)BATCH * NPIX * NPIX];  // [b][n][m]
__device__ __nv_bfloat16 g_attlo[(size_t)BATCH * NPIX * NPIX];
__device__ float g_outpre[(size_t)BATCH * CCH * NPIX];          // [b][c][n] fp32
__device__ float g_pool[2 * BATCH * CCH];
__device__ float g_gate[BATCH * CCH];

// ===========================================================================
// Baseline-PTX helpers (NO 'a'-suffix features: mma.sync / ldmatrix / cp.async)
// ===========================================================================
__device__ __forceinline__ uint32_t smem_u32(const void* p) {
    uint32_t a;
    asm("{ .reg .u64 t; cvta.to.shared.u64 t, %1; cvt.u32.u64 %0, t; }" : "=r"(a) : "l"(p));
    return a;
}
#define SWZ128(x) ((x) ^ (((x) >> 3) & 0x70))

__device__ __forceinline__ void cpa16(uint32_t s, const void* g) {
    asm volatile("cp.async.cg.shared.global [%0], [%1], 16;" :: "r"(s), "l"(g));
}
#define CP_COMMIT() asm volatile("cp.async.commit_group;" ::: "memory")
#define CP_WAIT0()  asm volatile("cp.async.wait_group 0;"  ::: "memory")

__device__ __forceinline__ void ldm4(uint32_t* r, uint32_t a) {
    asm volatile("ldmatrix.sync.aligned.m8n8.x4.shared.b16 {%0,%1,%2,%3}, [%4];"
        : "=r"(r[0]), "=r"(r[1]), "=r"(r[2]), "=r"(r[3]) : "r"(a));
}
__device__ __forceinline__ void mma16816(float* d, const uint32_t* a, const uint32_t* b) {
    asm volatile("mma.sync.aligned.m16n8k16.row.col.f32.bf16.bf16.f32 "
        "{%0,%1,%2,%3}, {%4,%5,%6,%7}, {%8,%9}, {%0,%1,%2,%3};"
        : "+f"(d[0]), "+f"(d[1]), "+f"(d[2]), "+f"(d[3])
        : "r"(a[0]), "r"(a[1]), "r"(a[2]), "r"(a[3]), "r"(b[0]), "r"(b[1]));
}

// ===========================================================================
// SMEM: 2 stages x (Ahi|Alo|Bhi|Blo), each 128 rows x 128B (KC=64 bf16), SW128.
// Epilogue reuses the region as a 128x132 fp32 staging tile.
// ===========================================================================
#define KC 64
#define STAGE_BYTES (4 * 16384)
#define OFF_AH(s) ((s) * STAGE_BYTES + 0)
#define OFF_AL(s) ((s) * STAGE_BYTES + 16384)
#define OFF_BH(s) ((s) * STAGE_BYTES + 32768)
#define OFF_BL(s) ((s) * STAGE_BYTES + 49152)
#define SMEM_BYTES (2 * STAGE_BYTES)     // 131072

__device__ __forceinline__ void ld_stage(uint32_t sb, int s,
    const __nv_bfloat16* __restrict__ Ahi, const __nv_bfloat16* __restrict__ Alo, int pitchA,
    const __nv_bfloat16* __restrict__ Bhi, const __nv_bfloat16* __restrict__ Blo, int pitchB,
    int k0, int tid)
{
#pragma unroll
    for (int t = 0; t < 4; t++) {
        int i = tid + t * 256;                  // 0..1023
        int row = i >> 3;
        int ch  = (i & 7) * 16;                 // byte offset within 128B row
        uint32_t so = SWZ128((uint32_t)(row * 128 + ch));
        cpa16(sb + OFF_AH(s) + so, (const char*)(Ahi + (size_t)row * pitchA + k0) + ch);
        cpa16(sb + OFF_AL(s) + so, (const char*)(Alo + (size_t)row * pitchA + k0) + ch);
        cpa16(sb + OFF_BH(s) + so, (const char*)(Bhi + (size_t)row * pitchB + k0) + ch);
        cpa16(sb + OFF_BL(s) + so, (const char*)(Blo + (size_t)row * pitchB + k0) + ch);
    }
}

// EPI: 0 = bias per col + split store   1 = bias per row + split store
//      2 = sigmoid + split store        3 = plain fp32 store
// SWAP: blockIdx.x indexes M (for L2-friendly rasterization on the bmm)
template<int KDIM, int EPI, bool SWAP>
__global__ __launch_bounds__(256, 1)
void mma_gemm(const __nv_bfloat16* __restrict__ Ahi, const __nv_bfloat16* __restrict__ Alo,
              int pitchA, long long sAb,
              const __nv_bfloat16* __restrict__ Bhi, const __nv_bfloat16* __restrict__ Blo,
              int pitchB, long long sBb,
              const float* __restrict__ bias,
              void* __restrict__ Cout, __nv_bfloat16* __restrict__ Clo,
              int pitchC, long long sCb)
{
    extern __shared__ char smem[];
    const uint32_t sb = smem_u32(smem);
    const int tid = threadIdx.x;
    const int bm = (SWAP ? blockIdx.x : blockIdx.y) * 128;
    const int bn = (SWAP ? blockIdx.y : blockIdx.x) * 128;
    const int b  = blockIdx.z;

    Ahi += (size_t)b * sAb + (size_t)bm * pitchA;
    Alo += (size_t)b * sAb + (size_t)bm * pitchA;
    Bhi += (size_t)b * sBb + (size_t)bn * pitchB;
    Blo += (size_t)b * sBb + (size_t)bn * pitchB;

    constexpr int NC = KDIM / KC;

    // warp decomposition: 8 warps = 4(M) x 2(N); warp tile 32(M) x 64(N)
    const int w  = tid >> 5, l = tid & 31;
    const int wm = (w & 3) * 32;
    const int wn = (w >> 2) * 64;

    // lane constants for ldmatrix addressing
    const int a_row   = l & 15;             // row within m16 tile
    const int a_kb    = (l >> 4) * 16;      // k-half byte offset
    const int b_noff  = ((l >> 4) & 1) * 8 + (l & 7);  // row within n16 pair
    const int b_kb    = ((l >> 3) & 1) * 16;           // k-half byte offset

    float acc[2][8][4];
#pragma unroll
    for (int i = 0; i < 2; i++)
#pragma unroll
        for (int j = 0; j < 8; j++)
#pragma unroll
            for (int q = 0; q < 4; q++) acc[i][j][q] = 0.f;

    ld_stage(sb, 0, Ahi, Alo, pitchA, Bhi, Blo, pitchB, 0, tid);
    CP_COMMIT();

    int buf = 0;
#pragma unroll 1
    for (int c = 0; c < NC; c++) {
        CP_WAIT0();
        __syncthreads();
        if (c + 1 < NC) {
            ld_stage(sb, buf ^ 1, Ahi, Alo, pitchA, Bhi, Blo, pitchB, (c + 1) * KC, tid);
            CP_COMMIT();
        }
        const uint32_t bAH = sb + OFF_AH(buf), bAL = sb + OFF_AL(buf);
        const uint32_t bBH = sb + OFF_BH(buf), bBL = sb + OFF_BL(buf);

#pragma unroll
        for (int ks = 0; ks < 4; ks++) {
            const int kb = ks * 32;
            uint32_t ah[2][4], al[2][4];
#pragma unroll
            for (int mt = 0; mt < 2; mt++) {
                uint32_t off = SWZ128((uint32_t)((wm + mt * 16 + a_row) * 128 + kb + a_kb));
                ldm4(ah[mt], bAH + off);
                ldm4(al[mt], bAL + off);
            }
            uint32_t bh[8][2], bl[8][2];
#pragma unroll
            for (int p = 0; p < 4; p++) {
                uint32_t off = SWZ128((uint32_t)((wn + p * 16 + b_noff) * 128 + kb + b_kb));
                uint32_t r[4];
                ldm4(r, bBH + off);
                bh[2 * p][0] = r[0]; bh[2 * p][1] = r[1];
                bh[2 * p + 1][0] = r[2]; bh[2 * p + 1][1] = r[3];
                ldm4(r, bBL + off);
                bl[2 * p][0] = r[0]; bl[2 * p][1] = r[1];
                bl[2 * p + 1][0] = r[2]; bl[2 * p + 1][1] = r[3];
            }
#pragma unroll
            for (int mt = 0; mt < 2; mt++)
#pragma unroll
                for (int nt = 0; nt < 8; nt++) {
                    mma16816(acc[mt][nt], ah[mt], bh[nt]);   // hi*hi
                    mma16816(acc[mt][nt], ah[mt], bl[nt]);   // hi*lo
                    mma16816(acc[mt][nt], al[mt], bh[nt]);   // lo*hi
                }
        }
        buf ^= 1;
    }
    __syncthreads();   // done reading operand SMEM; reuse as staging

    // ---- epilogue: regs -> SMEM stage (fp32, pitch 132) -> coalesced GMEM
    float* stage = (float*)smem;
    {
        const int qr = l >> 2, qc = (l & 3) * 2;
#pragma unroll
        for (int mt = 0; mt < 2; mt++)
#pragma unroll
            for (int nt = 0; nt < 8; nt++) {
                int r0 = wm + mt * 16 + qr;
                int c0 = wn + nt * 8 + qc;
                *(float2*)&stage[(size_t)r0 * 132 + c0] =
                    make_float2(acc[mt][nt][0], acc[mt][nt][1]);
                *(float2*)&stage[(size_t)(r0 + 8) * 132 + c0] =
                    make_float2(acc[mt][nt][2], acc[mt][nt][3]);
            }
    }
    __syncthreads();

    for (int g = tid; g < 2048; g += 256) {
        int row = g >> 4;
        int lc  = (g & 15) * 8;
        const float* st = stage + (size_t)row * 132 + lc;
        int orow = bm + row;
        int ncol = bn + lc;
        float v[8];
#pragma unroll
        for (int j = 0; j < 8; j++) {
            float x = st[j];
            if (EPI == 0) x += bias[ncol + j];
            if (EPI == 1) x += bias[orow];
            if (EPI == 2) x = __fdividef(1.f, 1.f + __expf(-x));
            v[j] = x;
        }
        if (EPI == 3) {
            float* dst = (float*)Cout + (size_t)b * sCb + (size_t)orow * pitchC + ncol;
            *(float4*)dst       = make_float4(v[0], v[1], v[2], v[3]);
            *(float4*)(dst + 4) = make_float4(v[4], v[5], v[6], v[7]);
        } else {
            uint16_t hb[8], lb[8];
#pragma unroll
            for (int j = 0; j < 8; j++) {
                __nv_bfloat16 h = __float2bfloat16(v[j]);
                __nv_bfloat16 lo = __float2bfloat16(v[j] - __bfloat162float(h));
                hb[j] = *(uint16_t*)&h;
                lb[j] = *(uint16_t*)&lo;
            }
            __nv_bfloat16* dh = (__nv_bfloat16*)Cout + (size_t)b * sCb + (size_t)orow * pitchC + ncol;
            __nv_bfloat16* dl = Clo                + (size_t)b * sCb + (size_t)orow * pitchC + ncol;
            *(uint4*)dh = *(uint4*)hb;
            *(uint4*)dl = *(uint4*)lb;
        }
    }
}

// ===========================================================================
// Prep kernels
// ===========================================================================
__global__ __launch_bounds__(256)
void transpose_split(const float* __restrict__ src,
                     __nv_bfloat16* __restrict__ dhi, __nv_bfloat16* __restrict__ dlo)
{
    __shared__ float t[32][33];
    const int b = blockIdx.z;
    const int n0 = blockIdx.x * 32, c0 = blockIdx.y * 32;
    const float* s = src + (size_t)b * CCH * NPIX;
    const int tx = threadIdx.x, ty = threadIdx.y;      // (32, 8)
#pragma unroll
    for (int j = 0; j < 32; j += 8)
        t[ty + j][tx] = s[(size_t)(c0 + ty + j) * NPIX + n0 + tx];
    __syncthreads();
    const size_t base = (size_t)b * NPIX * CCH;
#pragma unroll
    for (int j = 0; j < 32; j += 8) {
        float v = t[tx][ty + j];
        __nv_bfloat16 h = __float2bfloat16(v);
        __nv_bfloat16 l = __float2bfloat16(v - __bfloat162float(h));
        size_t off = base + (size_t)(n0 + ty + j) * CCH + c0 + tx;
        dhi[off] = h; dlo[off] = l;
    }
}

__global__ __launch_bounds__(256)
void prep_wqk(const float* __restrict__ Wq, const float* __restrict__ bq,
              const float* __restrict__ Wk, const float* __restrict__ bk,
              __nv_bfloat16* __restrict__ whi, __nv_bfloat16* __restrict__ wlo,
              float* __restrict__ bqk)
{
    int i = blockIdx.x * 256 + threadIdx.x;
    float v = (i < DCH * CCH) ? Wq[i] : Wk[i - DCH * CCH];
    __nv_bfloat16 h = __float2bfloat16(v);
    whi[i] = h; wlo[i] = __float2bfloat16(v - __bfloat162float(h));
    if (i < 2 * DCH) bqk[i] = (i < DCH) ? bq[i] : bk[i - DCH];
}

__global__ __launch_bounds__(256)
void prep_wv(const float* __restrict__ Wv,
             __nv_bfloat16* __restrict__ whi, __nv_bfloat16* __restrict__ wlo)
{
    int i = blockIdx.x * 256 + threadIdx.x;
    float v = Wv[i];
    __nv_bfloat16 h = __float2bfloat16(v);
    whi[i] = h; wlo[i] = __float2bfloat16(v - __bfloat162float(h));
}

// ===========================================================================
// Pool / gate / scale
// ===========================================================================
__global__ __launch_bounds__(256)
void pool_kernel(const float* __restrict__ outp, float* __restrict__ pool)
{
    const int row = blockIdx.x;
    const float4* p = (const float4*)(outp + (size_t)row * NPIX);
    const int tid = threadIdx.x;
    float s = 0.f, m = -3.402823466e38f;
    for (int i = tid; i < NPIX / 4; i += 256) {
        float4 v = p[i];
        s += v.x + v.y + v.z + v.w;
        m = fmaxf(m, fmaxf(fmaxf(v.x, v.y), fmaxf(v.z, v.w)));
    }
    __shared__ float ss[256], sm[256];
    ss[tid] = s; sm[tid] = m;
    __syncthreads();
    for (int off = 128; off > 0; off >>= 1) {
        if (tid < off) { ss[tid] += ss[tid + off]; sm[tid] = fmaxf(sm[tid], sm[tid + off]); }
        __syncthreads();
    }
    if (tid == 0) {
        pool[row]               = ss[0] * (1.f / NPIX);
        pool[BATCH * CCH + row] = sm[0];
    }
}

__global__ __launch_bounds__(256)
void gate_kernel(const float* __restrict__ pool,
                 const float* __restrict__ Wca1, const float* __restrict__ Wca2,
                 float* __restrict__ gate)
{
    const int b = blockIdx.x;
    const int tid = threadIdx.x;
    __shared__ float avg_s[CCH], max_s[CCH], h[RCH];
    for (int c = tid; c < CCH; c += 256) {
        avg_s[c] = pool[b * CCH + c];
        max_s[c] = pool[BATCH * CCH + b * CCH + c];
    }
    __syncthreads();
    for (int r = tid; r < RCH; r += 256) {
        float s1 = 0.f, s2 = 0.f;
        const float* w = Wca1 + (size_t)r * CCH;
        for (int c = 0; c < CCH; c++) { s1 += w[c] * avg_s[c]; s2 += w[c] * max_s[c]; }
        h[r] = fmaxf(s1, 0.f) + fmaxf(s2, 0.f);
    }
    __syncthreads();
    for (int c = tid; c < CCH; c += 256) {
        float g = 0.f;
        const float* w = Wca2 + (size_t)c * RCH;
#pragma unroll 8
        for (int r = 0; r < RCH; r++) g += w[r] * h[r];
        gate[b * CCH + c] = 1.f / (1.f + expf(-g));
    }
}

__global__ __launch_bounds__(256)
void scale_kernel(const float* __restrict__ outpre, const float* __restrict__ gate,
                  float* __restrict__ out)
{
    size_t i = (size_t)blockIdx.x * 256 + threadIdx.x;
    int row = (int)(i >> 10);
    float g = gate[row];
    float4 v = ((const float4*)outpre)[i];
    v.x *= g; v.y *= g; v.z *= g; v.w *= g;
    ((float4*)out)[i] = v;
}

// ===========================================================================
// Host launcher.  Inputs: x, x1, Wq, bq, Wk, bk, Wv, bv, Wca1, Wca2
// ===========================================================================
extern "C" void kernel_launch(void* const* d_in, const int* in_sizes, int n_in,
                              void* d_out, int out_size)
{
    const float* x    = (const float*)d_in[0];
    const float* x1   = (const float*)d_in[1];
    const float* Wq   = (const float*)d_in[2];
    const float* bq   = (const float*)d_in[3];
    const float* Wk   = (const float*)d_in[4];
    const float* bk   = (const float*)d_in[5];
    const float* Wv   = (const float*)d_in[6];
    const float* bv   = (const float*)d_in[7];
    const float* Wca1 = (const float*)d_in[8];
    const float* Wca2 = (const float*)d_in[9];
    float* out = (float*)d_out;

    static bool attr_done = false;
    if (!attr_done) {
        cudaFuncSetAttribute(mma_gemm<1024, 0, false>, cudaFuncAttributeMaxDynamicSharedMemorySize, SMEM_BYTES);
        cudaFuncSetAttribute(mma_gemm<1024, 1, false>, cudaFuncAttributeMaxDynamicSharedMemorySize, SMEM_BYTES);
        cudaFuncSetAttribute(mma_gemm<128,  2, false>, cudaFuncAttributeMaxDynamicSharedMemorySize, SMEM_BYTES);
        cudaFuncSetAttribute(mma_gemm<4096, 3, true >, cudaFuncAttributeMaxDynamicSharedMemorySize, SMEM_BYTES);
        attr_done = true;
    }

    void *pxh,*pxl,*p1h,*p1l,*pwh,*pwl,*pbqk,*pvh,*pvl,*pqh,*pql,*pVh,*pVl,*pah,*pal,*pop,*ppool,*pgate;
    cudaGetSymbolAddress(&pxh, g_xThi);  cudaGetSymbolAddress(&pxl, g_xTlo);
    cudaGetSymbolAddress(&p1h, g_x1Thi); cudaGetSymbolAddress(&p1l, g_x1Tlo);
    cudaGetSymbolAddress(&pwh, g_Wqkhi); cudaGetSymbolAddress(&pwl, g_Wqklo);
    cudaGetSymbolAddress(&pbqk, g_bqk);
    cudaGetSymbolAddress(&pvh, g_Wvhi);  cudaGetSymbolAddress(&pvl, g_Wvlo);
    cudaGetSymbolAddress(&pqh, g_QKThi); cudaGetSymbolAddress(&pql, g_QKTlo);
    cudaGetSymbolAddress(&pVh, g_Vhi);   cudaGetSymbolAddress(&pVl, g_Vlo);
    cudaGetSymbolAddress(&pah, g_atthi); cudaGetSymbolAddress(&pal, g_attlo);
    cudaGetSymbolAddress(&pop, g_outpre);
    cudaGetSymbolAddress(&ppool, g_pool); cudaGetSymbolAddress(&pgate, g_gate);

    dim3 thr(256);
    dim3 tthr(32, 8);

    // prep: transpose + bf16 hi/lo split
    transpose_split<<<dim3(NPIX / 32, CCH / 32, BATCH), tthr>>>(x,  (__nv_bfloat16*)pxh, (__nv_bfloat16*)pxl);
    transpose_split<<<dim3(NPIX / 32, CCH / 32, BATCH), tthr>>>(x1, (__nv_bfloat16*)p1h, (__nv_bfloat16*)p1l);
    prep_wqk<<<(2 * DCH * CCH) / 256, thr>>>(Wq, bq, Wk, bk,
        (__nv_bfloat16*)pwh, (__nv_bfloat16*)pwl, (float*)pbqk);
    prep_wv<<<(CCH * CCH) / 256, thr>>>(Wv, (__nv_bfloat16*)pvh, (__nv_bfloat16*)pvl);

    const long long sXT = (long long)NPIX * CCH;
    const long long sQK = (long long)NPIX * 2 * DCH;
    const long long sV  = (long long)CCH * NPIX;
    const long long sAT = (long long)NPIX * NPIX;

    // 1) QKT[n][0:256] = xT @ Wqk^T + bqk   (M=4096, N=256, K=1024)
    mma_gemm<1024, 0, false><<<dim3(2, 32, BATCH), thr, SMEM_BYTES>>>(
        (const __nv_bfloat16*)pxh, (const __nv_bfloat16*)pxl, CCH, sXT,
        (const __nv_bfloat16*)pwh, (const __nv_bfloat16*)pwl, CCH, 0LL,
        (const float*)pbqk, pqh, (__nv_bfloat16*)pql, 2 * DCH, sQK);

    // 2) V[c][m] = Wv @ x1 + bv             (M=1024, N=4096, K=1024)
    mma_gemm<1024, 1, false><<<dim3(32, 8, BATCH), thr, SMEM_BYTES>>>(
        (const __nv_bfloat16*)pvh, (const __nv_bfloat16*)pvl, CCH, 0LL,
        (const __nv_bfloat16*)p1h, (const __nv_bfloat16*)p1l, CCH, sXT,
        bv, pVh, (__nv_bfloat16*)pVl, NPIX, sV);

    // 3) att[n][m] = sigmoid(Q_n . K_m)     (M=4096, N=4096, K=128)
    mma_gemm<128, 2, false><<<dim3(32, 32, BATCH), thr, SMEM_BYTES>>>(
        (const __nv_bfloat16*)pqh,       (const __nv_bfloat16*)pql,       2 * DCH, sQK,
        (const __nv_bfloat16*)pqh + DCH, (const __nv_bfloat16*)pql + DCH, 2 * DCH, sQK,
        nullptr, pah, (__nv_bfloat16*)pal, NPIX, sAT);

    // 4) outpre[c][n] = sum_m V[c][m] att[n][m]  (M=1024, N=4096, K=4096)
    //    SWAP rasterization: x = M-blocks so att tiles are shared across
    //    consecutive CTAs and V (32MB) stays L2-resident.
    mma_gemm<4096, 3, true><<<dim3(8, 32, BATCH), thr, SMEM_BYTES>>>(
        (const __nv_bfloat16*)pVh, (const __nv_bfloat16*)pVl, NPIX, sV,
        (const __nv_bfloat16*)pah, (const __nv_bfloat16*)pal, NPIX, sAT,
        nullptr, pop, nullptr, NPIX, sV);

    // 5) tail
    pool_kernel<<<BATCH * CCH, thr>>>((const float*)pop, (float*)ppool);
    gate_kernel<<<BATCH, thr>>>((const float*)ppool, Wca1, Wca2, (float*)pgate);
    scale_kernel<<<(int)(((size_t)BATCH * CCH * NPIX / 4) / 256), thr>>>(
        (const float*)pop, (const float*)pgate, out);
}

// round 10
// speedup vs baseline: 6.0407x; 1.2361x over previous
#include <cuda_runtime.h>
#include <cuda_bf16.h>
#include <cuda_fp16.h>
#include <math.h>
#include <stdint.h>

#define BATCH 4
#define CCH   1024
#define DCH   128
#define RCH   64
#define NPIX  4096

// ===========================================================================
// Scratch (device globals — allocation-free)
// ===========================================================================
__device__ __nv_bfloat16 g_xThi [(size_t)BATCH * NPIX * CCH];   // x^T  [b][n][c]
__device__ __nv_bfloat16 g_xTlo [(size_t)BATCH * NPIX * CCH];
__device__ __nv_bfloat16 g_x1Thi[(size_t)BATCH * NPIX * CCH];   // x1^T [b][n][c]
__device__ __nv_bfloat16 g_x1Tlo[(size_t)BATCH * NPIX * CCH];
__device__ __nv_bfloat16 g_Wqkhi[(size_t)2 * DCH * CCH];        // [256][1024]
__device__ __nv_bfloat16 g_Wqklo[(size_t)2 * DCH * CCH];
__device__ float         g_bqk[2 * DCH];
__device__ __nv_bfloat16 g_Wvhi[(size_t)CCH * CCH];
__device__ __nv_bfloat16 g_Wvlo[(size_t)CCH * CCH];
__device__ __nv_bfloat16 g_QKThi[(size_t)BATCH * NPIX * 2 * DCH]; // [b][n][256] (Q 0-127, K 128-255)
__device__ __nv_bfloat16 g_QKTlo[(size_t)BATCH * NPIX * 2 * DCH];
__device__ __half g_Vhi16[(size_t)BATCH * CCH * NPIX];          // [b][c][m] fp16 hi
__device__ __half g_Vlo16[(size_t)BATCH * CCH * NPIX];          // fp16 lo
__device__ __half g_att16[(size_t)BATCH * NPIX * NPIX];         // [b][n][m] single fp16, 134MB
__device__ float g_outpre[(size_t)BATCH * CCH * NPIX];          // [b][c][n] fp32
__device__ float g_pool[2 * BATCH * CCH];
__device__ float g_gate[BATCH * CCH];

// ===========================================================================
// Baseline-PTX helpers (mma.sync / ldmatrix / cp.async only)
// ===========================================================================
__device__ __forceinline__ uint32_t smem_u32(const void* p) {
    uint32_t a;
    asm("{ .reg .u64 t; cvta.to.shared.u64 t, %1; cvt.u32.u64 %0, t; }" : "=r"(a) : "l"(p));
    return a;
}
#define SWZ128(x) ((x) ^ (((x) >> 3) & 0x70))

__device__ __forceinline__ void cpa16(uint32_t s, const void* g) {
    asm volatile("cp.async.cg.shared.global [%0], [%1], 16;" :: "r"(s), "l"(g));
}
#define CP_COMMIT() asm volatile("cp.async.commit_group;" ::: "memory")
#define CP_WAIT0()  asm volatile("cp.async.wait_group 0;"  ::: "memory")

__device__ __forceinline__ void ldm4(uint32_t* r, uint32_t a) {
    asm volatile("ldmatrix.sync.aligned.m8n8.x4.shared.b16 {%0,%1,%2,%3}, [%4];"
        : "=r"(r[0]), "=r"(r[1]), "=r"(r[2]), "=r"(r[3]) : "r"(a));
}
__device__ __forceinline__ void mma_bf(float* d, const uint32_t* a, const uint32_t* b) {
    asm volatile("mma.sync.aligned.m16n8k16.row.col.f32.bf16.bf16.f32 "
        "{%0,%1,%2,%3}, {%4,%5,%6,%7}, {%8,%9}, {%0,%1,%2,%3};"
        : "+f"(d[0]), "+f"(d[1]), "+f"(d[2]), "+f"(d[3])
        : "r"(a[0]), "r"(a[1]), "r"(a[2]), "r"(a[3]), "r"(b[0]), "r"(b[1]));
}
__device__ __forceinline__ void mma_fp(float* d, const uint32_t* a, const uint32_t* b) {
    asm volatile("mma.sync.aligned.m16n8k16.row.col.f32.f16.f16.f32 "
        "{%0,%1,%2,%3}, {%4,%5,%6,%7}, {%8,%9}, {%0,%1,%2,%3};"
        : "+f"(d[0]), "+f"(d[1]), "+f"(d[2]), "+f"(d[3])
        : "r"(a[0]), "r"(a[1]), "r"(a[2]), "r"(a[3]), "r"(b[0]), "r"(b[1]));
}

// ===========================================================================
// Tiled MMA GEMM.  CTA tile 128x128, KC=64 (128B SW128 rows), 2-stage cp.async.
// MODE 0: bf16 3-term (A hi/lo, B hi/lo)     stage = 4 x 16KB
// MODE 1: fp16 2-term (A hi/lo, B single)    stage = 3 x 16KB
// EPI: 0 = bias[col] + bf16 split store      1 = bias[row] + fp16 split store
//      2 = sigmoid + fp16 single store       3 = plain fp32 store
// SWAP: blockIdx.x indexes M (L2-friendly rasterization for the bmm)
// ===========================================================================
#define KC 64

template<int MODE> struct StageCfg {
    static constexpr int NOPS  = (MODE == 0) ? 4 : 3;
    static constexpr int BYTES = NOPS * 16384;
};

template<int MODE>
__device__ __forceinline__ void ld_stage(uint32_t sb, int s,
    const uint16_t* __restrict__ Ahi, const uint16_t* __restrict__ Alo, int pitchA,
    const uint16_t* __restrict__ Bhi, const uint16_t* __restrict__ Blo, int pitchB,
    int k0, int tid)
{
    const uint32_t base = sb + s * StageCfg<MODE>::BYTES;
#pragma unroll
    for (int t = 0; t < 4; t++) {
        int i = tid + t * 256;                  // 0..1023
        int row = i >> 3;
        int ch  = (i & 7) * 16;                 // byte offset within 128B row
        uint32_t so = SWZ128((uint32_t)(row * 128 + ch));
        cpa16(base + so,         (const char*)(Ahi + (size_t)row * pitchA + k0) + ch);
        cpa16(base + 16384 + so, (const char*)(Alo + (size_t)row * pitchA + k0) + ch);
        cpa16(base + 32768 + so, (const char*)(Bhi + (size_t)row * pitchB + k0) + ch);
        if (MODE == 0)
            cpa16(base + 49152 + so, (const char*)(Blo + (size_t)row * pitchB + k0) + ch);
    }
}

template<int KDIM, int EPI, bool SWAP, int MODE>
__global__ __launch_bounds__(256, 1)
void mma_gemm(const uint16_t* __restrict__ Ahi, const uint16_t* __restrict__ Alo,
              int pitchA, long long sAb,
              const uint16_t* __restrict__ Bhi, const uint16_t* __restrict__ Blo,
              int pitchB, long long sBb,
              const float* __restrict__ bias,
              void* __restrict__ Cout, void* __restrict__ Clo,
              int pitchC, long long sCb)
{
    extern __shared__ char smem[];
    const uint32_t sb = smem_u32(smem);
    const int tid = threadIdx.x;
    const int bm = (SWAP ? blockIdx.x : blockIdx.y) * 128;
    const int bn = (SWAP ? blockIdx.y : blockIdx.x) * 128;
    const int b  = blockIdx.z;

    Ahi += (size_t)b * sAb + (size_t)bm * pitchA;
    Alo += (size_t)b * sAb + (size_t)bm * pitchA;
    Bhi += (size_t)b * sBb + (size_t)bn * pitchB;
    if (MODE == 0) Blo += (size_t)b * sBb + (size_t)bn * pitchB;

    constexpr int NC = KDIM / KC;
    constexpr int SBYTES = StageCfg<MODE>::BYTES;

    // 8 warps = 4(M) x 2(N); warp tile 32(M) x 64(N)
    const int w  = tid >> 5, l = tid & 31;
    const int wm = (w & 3) * 32;
    const int wn = (w >> 2) * 64;

    const int a_row  = l & 15;
    const int a_kb   = (l >> 4) * 16;
    const int b_noff = ((l >> 4) & 1) * 8 + (l & 7);
    const int b_kb   = ((l >> 3) & 1) * 16;

    float acc[2][8][4];
#pragma unroll
    for (int i = 0; i < 2; i++)
#pragma unroll
        for (int j = 0; j < 8; j++)
#pragma unroll
            for (int q = 0; q < 4; q++) acc[i][j][q] = 0.f;

    ld_stage<MODE>(sb, 0, Ahi, Alo, pitchA, Bhi, Blo, pitchB, 0, tid);
    CP_COMMIT();

    int buf = 0;
#pragma unroll 1
    for (int c = 0; c < NC; c++) {
        CP_WAIT0();
        __syncthreads();
        if (c + 1 < NC) {
            ld_stage<MODE>(sb, buf ^ 1, Ahi, Alo, pitchA, Bhi, Blo, pitchB, (c + 1) * KC, tid);
            CP_COMMIT();
        }
        const uint32_t bAH = sb + buf * SBYTES;
        const uint32_t bAL = bAH + 16384;
        const uint32_t bBH = bAH + 32768;
        const uint32_t bBL = bAH + 49152;   // MODE 0 only

#pragma unroll
        for (int ks = 0; ks < 4; ks++) {
            const int kb = ks * 32;
            uint32_t ah[2][4], al[2][4];
#pragma unroll
            for (int mt = 0; mt < 2; mt++) {
                uint32_t off = SWZ128((uint32_t)((wm + mt * 16 + a_row) * 128 + kb + a_kb));
                ldm4(ah[mt], bAH + off);
                ldm4(al[mt], bAL + off);
            }
            uint32_t bh[8][2];
            uint32_t bl[8][2];
#pragma unroll
            for (int p = 0; p < 4; p++) {
                uint32_t off = SWZ128((uint32_t)((wn + p * 16 + b_noff) * 128 + kb + b_kb));
                uint32_t r[4];
                ldm4(r, bBH + off);
                bh[2 * p][0] = r[0]; bh[2 * p][1] = r[1];
                bh[2 * p + 1][0] = r[2]; bh[2 * p + 1][1] = r[3];
                if (MODE == 0) {
                    ldm4(r, bBL + off);
                    bl[2 * p][0] = r[0]; bl[2 * p][1] = r[1];
                    bl[2 * p + 1][0] = r[2]; bl[2 * p + 1][1] = r[3];
                }
            }
#pragma unroll
            for (int mt = 0; mt < 2; mt++)
#pragma unroll
                for (int nt = 0; nt < 8; nt++) {
                    if (MODE == 0) {
                        mma_bf(acc[mt][nt], ah[mt], bh[nt]);   // hi*hi
                        mma_bf(acc[mt][nt], ah[mt], bl[nt]);   // hi*lo
                        mma_bf(acc[mt][nt], al[mt], bh[nt]);   // lo*hi
                    } else {
                        mma_fp(acc[mt][nt], ah[mt], bh[nt]);   // Vhi*att
                        mma_fp(acc[mt][nt], al[mt], bh[nt]);   // Vlo*att
                    }
                }
        }
        buf ^= 1;
    }
    __syncthreads();   // operand SMEM now reusable as staging

    // ---- epilogue: regs -> SMEM stage (fp32, pitch 132) -> coalesced GMEM
    float* stage = (float*)smem;
    {
        const int qr = l >> 2, qc = (l & 3) * 2;
#pragma unroll
        for (int mt = 0; mt < 2; mt++)
#pragma unroll
            for (int nt = 0; nt < 8; nt++) {
                int r0 = wm + mt * 16 + qr;
                int c0 = wn + nt * 8 + qc;
                *(float2*)&stage[(size_t)r0 * 132 + c0] =
                    make_float2(acc[mt][nt][0], acc[mt][nt][1]);
                *(float2*)&stage[(size_t)(r0 + 8) * 132 + c0] =
                    make_float2(acc[mt][nt][2], acc[mt][nt][3]);
            }
    }
    __syncthreads();

    for (int g = tid; g < 2048; g += 256) {
        int row = g >> 4;
        int lc  = (g & 15) * 8;
        const float* st = stage + (size_t)row * 132 + lc;
        int orow = bm + row;
        int ncol = bn + lc;
        float v[8];
#pragma unroll
        for (int j = 0; j < 8; j++) {
            float x = st[j];
            if (EPI == 0) x += bias[ncol + j];
            if (EPI == 1) x += bias[orow];
            if (EPI == 2) x = __fdividef(1.f, 1.f + __expf(-x));
            v[j] = x;
        }
        size_t dsto = (size_t)b * sCb + (size_t)orow * pitchC + ncol;
        if (EPI == 3) {
            float* dst = (float*)Cout + dsto;
            *(float4*)dst       = make_float4(v[0], v[1], v[2], v[3]);
            *(float4*)(dst + 4) = make_float4(v[4], v[5], v[6], v[7]);
        } else if (EPI == 2) {
            uint16_t hb[8];
#pragma unroll
            for (int j = 0; j < 8; j++) {
                __half h = __float2half(v[j]);
                hb[j] = *(uint16_t*)&h;
            }
            *(uint4*)((__half*)Cout + dsto) = *(uint4*)hb;
        } else if (EPI == 1) {
            uint16_t hb[8], lb[8];
#pragma unroll
            for (int j = 0; j < 8; j++) {
                __half h = __float2half(v[j]);
                __half lo = __float2half(v[j] - __half2float(h));
                hb[j] = *(uint16_t*)&h;
                lb[j] = *(uint16_t*)&lo;
            }
            *(uint4*)((__half*)Cout + dsto) = *(uint4*)hb;
            *(uint4*)((__half*)Clo  + dsto) = *(uint4*)lb;
        } else {
            uint16_t hb[8], lb[8];
#pragma unroll
            for (int j = 0; j < 8; j++) {
                __nv_bfloat16 h = __float2bfloat16(v[j]);
                __nv_bfloat16 lo = __float2bfloat16(v[j] - __bfloat162float(h));
                hb[j] = *(uint16_t*)&h;
                lb[j] = *(uint16_t*)&lo;
            }
            *(uint4*)((__nv_bfloat16*)Cout + dsto) = *(uint4*)hb;
            *(uint4*)((__nv_bfloat16*)Clo  + dsto) = *(uint4*)lb;
        }
    }
}

// ===========================================================================
// Prep kernels
// ===========================================================================
__global__ __launch_bounds__(256)
void transpose_split(const float* __restrict__ src,
                     __nv_bfloat16* __restrict__ dhi, __nv_bfloat16* __restrict__ dlo)
{
    __shared__ float t[32][33];
    const int b = blockIdx.z;
    const int n0 = blockIdx.x * 32, c0 = blockIdx.y * 32;
    const float* s = src + (size_t)b * CCH * NPIX;
    const int tx = threadIdx.x, ty = threadIdx.y;      // (32, 8)
#pragma unroll
    for (int j = 0; j < 32; j += 8)
        t[ty + j][tx] = s[(size_t)(c0 + ty + j) * NPIX + n0 + tx];
    __syncthreads();
    const size_t base = (size_t)b * NPIX * CCH;
#pragma unroll
    for (int j = 0; j < 32; j += 8) {
        float v = t[tx][ty + j];
        __nv_bfloat16 h = __float2bfloat16(v);
        __nv_bfloat16 l = __float2bfloat16(v - __bfloat162float(h));
        size_t off = base + (size_t)(n0 + ty + j) * CCH + c0 + tx;
        dhi[off] = h; dlo[off] = l;
    }
}

__global__ __launch_bounds__(256)
void prep_wqk(const float* __restrict__ Wq, const float* __restrict__ bq,
              const float* __restrict__ Wk, const float* __restrict__ bk,
              __nv_bfloat16* __restrict__ whi, __nv_bfloat16* __restrict__ wlo,
              float* __restrict__ bqk)
{
    int i = blockIdx.x * 256 + threadIdx.x;
    float v = (i < DCH * CCH) ? Wq[i] : Wk[i - DCH * CCH];
    __nv_bfloat16 h = __float2bfloat16(v);
    whi[i] = h; wlo[i] = __float2bfloat16(v - __bfloat162float(h));
    if (i < 2 * DCH) bqk[i] = (i < DCH) ? bq[i] : bk[i - DCH];
}

__global__ __launch_bounds__(256)
void prep_wv(const float* __restrict__ Wv,
             __nv_bfloat16* __restrict__ whi, __nv_bfloat16* __restrict__ wlo)
{
    int i = blockIdx.x * 256 + threadIdx.x;
    float v = Wv[i];
    __nv_bfloat16 h = __float2bfloat16(v);
    whi[i] = h; wlo[i] = __float2bfloat16(v - __bfloat162float(h));
}

// ===========================================================================
// Pool / gate / scale
// ===========================================================================
__global__ __launch_bounds__(256)
void pool_kernel(const float* __restrict__ outp, float* __restrict__ pool)
{
    const int row = blockIdx.x;
    const float4* p = (const float4*)(outp + (size_t)row * NPIX);
    const int tid = threadIdx.x;
    float s = 0.f, m = -3.402823466e38f;
    for (int i = tid; i < NPIX / 4; i += 256) {
        float4 v = p[i];
        s += v.x + v.y + v.z + v.w;
        m = fmaxf(m, fmaxf(fmaxf(v.x, v.y), fmaxf(v.z, v.w)));
    }
    __shared__ float ss[256], sm[256];
    ss[tid] = s; sm[tid] = m;
    __syncthreads();
    for (int off = 128; off > 0; off >>= 1) {
        if (tid < off) { ss[tid] += ss[tid + off]; sm[tid] = fmaxf(sm[tid], sm[tid + off]); }
        __syncthreads();
    }
    if (tid == 0) {
        pool[row]               = ss[0] * (1.f / NPIX);
        pool[BATCH * CCH + row] = sm[0];
    }
}

__global__ __launch_bounds__(256)
void gate_kernel(const float* __restrict__ pool,
                 const float* __restrict__ Wca1, const float* __restrict__ Wca2,
                 float* __restrict__ gate)
{
    const int b = blockIdx.x;
    const int tid = threadIdx.x;
    __shared__ float avg_s[CCH], max_s[CCH], h[RCH];
    for (int c = tid; c < CCH; c += 256) {
        avg_s[c] = pool[b * CCH + c];
        max_s[c] = pool[BATCH * CCH + b * CCH + c];
    }
    __syncthreads();
    for (int r = tid; r < RCH; r += 256) {
        float s1 = 0.f, s2 = 0.f;
        const float* w = Wca1 + (size_t)r * CCH;
        for (int c = 0; c < CCH; c++) { s1 += w[c] * avg_s[c]; s2 += w[c] * max_s[c]; }
        h[r] = fmaxf(s1, 0.f) + fmaxf(s2, 0.f);
    }
    __syncthreads();
    for (int c = tid; c < CCH; c += 256) {
        float g = 0.f;
        const float* w = Wca2 + (size_t)c * RCH;
#pragma unroll 8
        for (int r = 0; r < RCH; r++) g += w[r] * h[r];
        gate[b * CCH + c] = 1.f / (1.f + expf(-g));
    }
}

__global__ __launch_bounds__(256)
void scale_kernel(const float* __restrict__ outpre, const float* __restrict__ gate,
                  float* __restrict__ out)
{
    size_t i = (size_t)blockIdx.x * 256 + threadIdx.x;
    int row = (int)(i >> 10);
    float g = gate[row];
    float4 v = ((const float4*)outpre)[i];
    v.x *= g; v.y *= g; v.z *= g; v.w *= g;
    ((float4*)out)[i] = v;
}

// ===========================================================================
// Host launcher.  Inputs: x, x1, Wq, bq, Wk, bk, Wv, bv, Wca1, Wca2
// ===========================================================================
extern "C" void kernel_launch(void* const* d_in, const int* in_sizes, int n_in,
                              void* d_out, int out_size)
{
    const float* x    = (const float*)d_in[0];
    const float* x1   = (const float*)d_in[1];
    const float* Wq   = (const float*)d_in[2];
    const float* bq   = (const float*)d_in[3];
    const float* Wk   = (const float*)d_in[4];
    const float* bk   = (const float*)d_in[5];
    const float* Wv   = (const float*)d_in[6];
    const float* bv   = (const float*)d_in[7];
    const float* Wca1 = (const float*)d_in[8];
    const float* Wca2 = (const float*)d_in[9];
    float* out = (float*)d_out;

    constexpr int SM0 = StageCfg<0>::BYTES * 2;   // 131072
    constexpr int SM1 = StageCfg<1>::BYTES * 2;   //  98304

    static bool attr_done = false;
    if (!attr_done) {
        cudaFuncSetAttribute(mma_gemm<1024, 0, false, 0>, cudaFuncAttributeMaxDynamicSharedMemorySize, SM0);
        cudaFuncSetAttribute(mma_gemm<1024, 1, false, 0>, cudaFuncAttributeMaxDynamicSharedMemorySize, SM0);
        cudaFuncSetAttribute(mma_gemm<128,  2, false, 0>, cudaFuncAttributeMaxDynamicSharedMemorySize, SM0);
        cudaFuncSetAttribute(mma_gemm<4096, 3, true,  1>, cudaFuncAttributeMaxDynamicSharedMemorySize, SM1);
        attr_done = true;
    }

    void *pxh,*pxl,*p1h,*p1l,*pwh,*pwl,*pbqk,*pvh,*pvl,*pqh,*pql,*pVh,*pVl,*pat,*pop,*ppool,*pgate;
    cudaGetSymbolAddress(&pxh, g_xThi);  cudaGetSymbolAddress(&pxl, g_xTlo);
    cudaGetSymbolAddress(&p1h, g_x1Thi); cudaGetSymbolAddress(&p1l, g_x1Tlo);
    cudaGetSymbolAddress(&pwh, g_Wqkhi); cudaGetSymbolAddress(&pwl, g_Wqklo);
    cudaGetSymbolAddress(&pbqk, g_bqk);
    cudaGetSymbolAddress(&pvh, g_Wvhi);  cudaGetSymbolAddress(&pvl, g_Wvlo);
    cudaGetSymbolAddress(&pqh, g_QKThi); cudaGetSymbolAddress(&pql, g_QKTlo);
    cudaGetSymbolAddress(&pVh, g_Vhi16); cudaGetSymbolAddress(&pVl, g_Vlo16);
    cudaGetSymbolAddress(&pat, g_att16);
    cudaGetSymbolAddress(&pop, g_outpre);
    cudaGetSymbolAddress(&ppool, g_pool); cudaGetSymbolAddress(&pgate, g_gate);

    dim3 thr(256);
    dim3 tthr(32, 8);

    // prep: transpose + bf16 hi/lo split
    transpose_split<<<dim3(NPIX / 32, CCH / 32, BATCH), tthr>>>(x,  (__nv_bfloat16*)pxh, (__nv_bfloat16*)pxl);
    transpose_split<<<dim3(NPIX / 32, CCH / 32, BATCH), tthr>>>(x1, (__nv_bfloat16*)p1h, (__nv_bfloat16*)p1l);
    prep_wqk<<<(2 * DCH * CCH) / 256, thr>>>(Wq, bq, Wk, bk,
        (__nv_bfloat16*)pwh, (__nv_bfloat16*)pwl, (float*)pbqk);
    prep_wv<<<(CCH * CCH) / 256, thr>>>(Wv, (__nv_bfloat16*)pvh, (__nv_bfloat16*)pvl);

    const long long sXT = (long long)NPIX * CCH;
    const long long sQK = (long long)NPIX * 2 * DCH;
    const long long sV  = (long long)CCH * NPIX;
    const long long sAT = (long long)NPIX * NPIX;

    // 1) QKT[n][0:256] = xT @ Wqk^T + bqk   (M=4096, N=256, K=1024) bf16 3-term
    mma_gemm<1024, 0, false, 0><<<dim3(2, 32, BATCH), thr, SM0>>>(
        (const uint16_t*)pxh, (const uint16_t*)pxl, CCH, sXT,
        (const uint16_t*)pwh, (const uint16_t*)pwl, CCH, 0LL,
        (const float*)pbqk, pqh, pql, 2 * DCH, sQK);

    // 2) V[c][m] = Wv @ x1 + bv             (M=1024, N=4096, K=1024) bf16 3-term -> fp16 hi/lo out
    mma_gemm<1024, 1, false, 0><<<dim3(32, 8, BATCH), thr, SM0>>>(
        (const uint16_t*)pvh, (const uint16_t*)pvl, CCH, 0LL,
        (const uint16_t*)p1h, (const uint16_t*)p1l, CCH, sXT,
        bv, pVh, pVl, NPIX, sV);

    // 3) att[n][m] = sigmoid(Q_n . K_m)     (M=4096, N=4096, K=128) bf16 3-term -> fp16 single out
    mma_gemm<128, 2, false, 0><<<dim3(32, 32, BATCH), thr, SM0>>>(
        (const uint16_t*)pqh,       (const uint16_t*)pql,       2 * DCH, sQK,
        (const uint16_t*)pqh + DCH, (const uint16_t*)pql + DCH, 2 * DCH, sQK,
        nullptr, pat, nullptr, NPIX, sAT);

    // 4) outpre[c][n] = sum_m V[c][m] att[n][m]  (M=1024, N=4096, K=4096)
    //    fp16 2-term (V hi/lo x att single); SWAP rasterization keeps V L2-resident.
    mma_gemm<4096, 3, true, 1><<<dim3(8, 32, BATCH), thr, SM1>>>(
        (const uint16_t*)pVh, (const uint16_t*)pVl, NPIX, sV,
        (const uint16_t*)pat, nullptr, NPIX, sAT,
        nullptr, pop, nullptr, NPIX, sV);

    // 5) tail
    pool_kernel<<<BATCH * CCH, thr>>>((const float*)pop, (float*)ppool);
    gate_kernel<<<BATCH, thr>>>((const float*)ppool, Wca1, Wca2, (float*)pgate);
    scale_kernel<<<(int)(((size_t)BATCH * CCH * NPIX / 4) / 256), thr>>>(
        (const float*)pop, (const float*)pgate, out);
}

// round 11
// speedup vs baseline: 6.3639x; 1.0535x over previous
#include <cuda_runtime.h>
#include <cuda_bf16.h>
#include <cuda_fp16.h>
#include <math.h>
#include <stdint.h>
#include <float.h>

#define BATCH 4
#define CCH   1024
#define DCH   128
#define RCH   64
#define NPIX  4096
#define NBLK  32              // N-blocks in the bmm (4096/128)

// ===========================================================================
// Scratch (device globals — allocation-free)
// ===========================================================================
__device__ __nv_bfloat16 g_xThi [(size_t)BATCH * NPIX * CCH];   // x^T  [b][n][c] bf16 hi
__device__ __nv_bfloat16 g_xTlo [(size_t)BATCH * NPIX * CCH];
__device__ __half        g_x1T  [(size_t)BATCH * NPIX * CCH];   // x1^T [b][n][c] fp16 single
__device__ __nv_bfloat16 g_Wqkhi[(size_t)2 * DCH * CCH];        // [256][1024]
__device__ __nv_bfloat16 g_Wqklo[(size_t)2 * DCH * CCH];
__device__ float         g_bqk[2 * DCH];
__device__ __half g_Wvhi16[(size_t)CCH * CCH];                  // Wv fp16 hi
__device__ __half g_Wvlo16[(size_t)CCH * CCH];                  // Wv fp16 lo
__device__ __nv_bfloat16 g_QKThi[(size_t)BATCH * NPIX * 2 * DCH]; // [b][n][256]
__device__ __nv_bfloat16 g_QKTlo[(size_t)BATCH * NPIX * 2 * DCH];
__device__ __half g_Vhi16[(size_t)BATCH * CCH * NPIX];          // [b][c][m] fp16 hi
__device__ __half g_Vlo16[(size_t)BATCH * CCH * NPIX];          // fp16 lo
__device__ __half g_att16[(size_t)BATCH * NPIX * NPIX];         // [b][n][m] fp16
__device__ float g_outpre[(size_t)BATCH * CCH * NPIX];          // [b][c][n] fp32
__device__ float g_ppool[2 * BATCH * NBLK * CCH];               // partial sums | partial maxes
__device__ float g_gate[BATCH * CCH];

// ===========================================================================
// Baseline-PTX helpers (mma.sync / ldmatrix / cp.async only)
// ===========================================================================
__device__ __forceinline__ uint32_t smem_u32(const void* p) {
    uint32_t a;
    asm("{ .reg .u64 t; cvta.to.shared.u64 t, %1; cvt.u32.u64 %0, t; }" : "=r"(a) : "l"(p));
    return a;
}
#define SWZ128(x) ((x) ^ (((x) >> 3) & 0x70))

__device__ __forceinline__ void cpa16(uint32_t s, const void* g) {
    asm volatile("cp.async.cg.shared.global [%0], [%1], 16;" :: "r"(s), "l"(g));
}
#define CP_COMMIT() asm volatile("cp.async.commit_group;" ::: "memory")
#define CP_WAIT0()  asm volatile("cp.async.wait_group 0;"  ::: "memory")

__device__ __forceinline__ void ldm4(uint32_t* r, uint32_t a) {
    asm volatile("ldmatrix.sync.aligned.m8n8.x4.shared.b16 {%0,%1,%2,%3}, [%4];"
        : "=r"(r[0]), "=r"(r[1]), "=r"(r[2]), "=r"(r[3]) : "r"(a));
}
__device__ __forceinline__ void mma_bf(float* d, const uint32_t* a, const uint32_t* b) {
    asm volatile("mma.sync.aligned.m16n8k16.row.col.f32.bf16.bf16.f32 "
        "{%0,%1,%2,%3}, {%4,%5,%6,%7}, {%8,%9}, {%0,%1,%2,%3};"
        : "+f"(d[0]), "+f"(d[1]), "+f"(d[2]), "+f"(d[3])
        : "r"(a[0]), "r"(a[1]), "r"(a[2]), "r"(a[3]), "r"(b[0]), "r"(b[1]));
}
__device__ __forceinline__ void mma_fp(float* d, const uint32_t* a, const uint32_t* b) {
    asm volatile("mma.sync.aligned.m16n8k16.row.col.f32.f16.f16.f32 "
        "{%0,%1,%2,%3}, {%4,%5,%6,%7}, {%8,%9}, {%0,%1,%2,%3};"
        : "+f"(d[0]), "+f"(d[1]), "+f"(d[2]), "+f"(d[3])
        : "r"(a[0]), "r"(a[1]), "r"(a[2]), "r"(a[3]), "r"(b[0]), "r"(b[1]));
}

// ===========================================================================
// Tiled MMA GEMM.  CTA tile 128x128, KC=64 (128B SW128 rows), 2-stage cp.async.
// MODE 0: bf16 3-term (A hi/lo, B hi/lo)     stage = 4 x 16KB
// MODE 1: fp16 2-term (A hi/lo, B single)    stage = 3 x 16KB
// EPI: 0 = bias[col] + bf16 split store      1 = bias[row] + fp16 split store
//      2 = sigmoid + fp16 single store       3 = plain fp32 store
//      4 = fp32 store + per-CTA partial row pooling (sum & max over 128 cols)
// SWAP: blockIdx.x indexes M (L2-friendly rasterization for the bmm)
// ===========================================================================
#define KC 64

template<int MODE> struct StageCfg {
    static constexpr int NOPS  = (MODE == 0) ? 4 : 3;
    static constexpr int BYTES = NOPS * 16384;
};

template<int MODE>
__device__ __forceinline__ void ld_stage(uint32_t sb, int s,
    const uint16_t* __restrict__ Ahi, const uint16_t* __restrict__ Alo, int pitchA,
    const uint16_t* __restrict__ Bhi, const uint16_t* __restrict__ Blo, int pitchB,
    int k0, int tid)
{
    const uint32_t base = sb + s * StageCfg<MODE>::BYTES;
#pragma unroll
    for (int t = 0; t < 4; t++) {
        int i = tid + t * 256;                  // 0..1023
        int row = i >> 3;
        int ch  = (i & 7) * 16;                 // byte offset within 128B row
        uint32_t so = SWZ128((uint32_t)(row * 128 + ch));
        cpa16(base + so,         (const char*)(Ahi + (size_t)row * pitchA + k0) + ch);
        cpa16(base + 16384 + so, (const char*)(Alo + (size_t)row * pitchA + k0) + ch);
        cpa16(base + 32768 + so, (const char*)(Bhi + (size_t)row * pitchB + k0) + ch);
        if (MODE == 0)
            cpa16(base + 49152 + so, (const char*)(Blo + (size_t)row * pitchB + k0) + ch);
    }
}

template<int KDIM, int EPI, bool SWAP, int MODE>
__global__ __launch_bounds__(256, 1)
void mma_gemm(const uint16_t* __restrict__ Ahi, const uint16_t* __restrict__ Alo,
              int pitchA, long long sAb,
              const uint16_t* __restrict__ Bhi, const uint16_t* __restrict__ Blo,
              int pitchB, long long sBb,
              const float* __restrict__ bias,
              void* __restrict__ Cout, void* __restrict__ Caux,
              int pitchC, long long sCb)
{
    extern __shared__ char smem[];
    const uint32_t sb = smem_u32(smem);
    const int tid = threadIdx.x;
    const int bm = (SWAP ? blockIdx.x : blockIdx.y) * 128;
    const int bn = (SWAP ? blockIdx.y : blockIdx.x) * 128;
    const int b  = blockIdx.z;

    Ahi += (size_t)b * sAb + (size_t)bm * pitchA;
    Alo += (size_t)b * sAb + (size_t)bm * pitchA;
    Bhi += (size_t)b * sBb + (size_t)bn * pitchB;
    if (MODE == 0) Blo += (size_t)b * sBb + (size_t)bn * pitchB;

    constexpr int NC = KDIM / KC;
    constexpr int SBYTES = StageCfg<MODE>::BYTES;

    // 8 warps = 4(M) x 2(N); warp tile 32(M) x 64(N)
    const int w  = tid >> 5, l = tid & 31;
    const int wm = (w & 3) * 32;
    const int wn = (w >> 2) * 64;

    const int a_row  = l & 15;
    const int a_kb   = (l >> 4) * 16;
    const int b_noff = ((l >> 4) & 1) * 8 + (l & 7);
    const int b_kb   = ((l >> 3) & 1) * 16;

    float acc[2][8][4];
#pragma unroll
    for (int i = 0; i < 2; i++)
#pragma unroll
        for (int j = 0; j < 8; j++)
#pragma unroll
            for (int q = 0; q < 4; q++) acc[i][j][q] = 0.f;

    ld_stage<MODE>(sb, 0, Ahi, Alo, pitchA, Bhi, Blo, pitchB, 0, tid);
    CP_COMMIT();

    int buf = 0;
#pragma unroll 1
    for (int c = 0; c < NC; c++) {
        CP_WAIT0();
        __syncthreads();
        if (c + 1 < NC) {
            ld_stage<MODE>(sb, buf ^ 1, Ahi, Alo, pitchA, Bhi, Blo, pitchB, (c + 1) * KC, tid);
            CP_COMMIT();
        }
        const uint32_t bAH = sb + buf * SBYTES;
        const uint32_t bAL = bAH + 16384;
        const uint32_t bBH = bAH + 32768;
        const uint32_t bBL = bAH + 49152;   // MODE 0 only

#pragma unroll
        for (int ks = 0; ks < 4; ks++) {
            const int kb = ks * 32;
            uint32_t ah[2][4], al[2][4];
#pragma unroll
            for (int mt = 0; mt < 2; mt++) {
                uint32_t off = SWZ128((uint32_t)((wm + mt * 16 + a_row) * 128 + kb + a_kb));
                ldm4(ah[mt], bAH + off);
                ldm4(al[mt], bAL + off);
            }
            uint32_t bh[8][2];
            uint32_t bl[8][2];
#pragma unroll
            for (int p = 0; p < 4; p++) {
                uint32_t off = SWZ128((uint32_t)((wn + p * 16 + b_noff) * 128 + kb + b_kb));
                uint32_t r[4];
                ldm4(r, bBH + off);
                bh[2 * p][0] = r[0]; bh[2 * p][1] = r[1];
                bh[2 * p + 1][0] = r[2]; bh[2 * p + 1][1] = r[3];
                if (MODE == 0) {
                    ldm4(r, bBL + off);
                    bl[2 * p][0] = r[0]; bl[2 * p][1] = r[1];
                    bl[2 * p + 1][0] = r[2]; bl[2 * p + 1][1] = r[3];
                }
            }
#pragma unroll
            for (int mt = 0; mt < 2; mt++)
#pragma unroll
                for (int nt = 0; nt < 8; nt++) {
                    if (MODE == 0) {
                        mma_bf(acc[mt][nt], ah[mt], bh[nt]);   // hi*hi
                        mma_bf(acc[mt][nt], ah[mt], bl[nt]);   // hi*lo
                        mma_bf(acc[mt][nt], al[mt], bh[nt]);   // lo*hi
                    } else {
                        mma_fp(acc[mt][nt], ah[mt], bh[nt]);   // hi*B
                        mma_fp(acc[mt][nt], al[mt], bh[nt]);   // lo*B
                    }
                }
        }
        buf ^= 1;
    }
    __syncthreads();   // operand SMEM now reusable as staging

    // ---- epilogue: regs -> SMEM stage (fp32, pitch 132) -> coalesced GMEM
    float* stage = (float*)smem;
    {
        const int qr = l >> 2, qc = (l & 3) * 2;
#pragma unroll
        for (int mt = 0; mt < 2; mt++)
#pragma unroll
            for (int nt = 0; nt < 8; nt++) {
                int r0 = wm + mt * 16 + qr;
                int c0 = wn + nt * 8 + qc;
                *(float2*)&stage[(size_t)r0 * 132 + c0] =
                    make_float2(acc[mt][nt][0], acc[mt][nt][1]);
                *(float2*)&stage[(size_t)(r0 + 8) * 132 + c0] =
                    make_float2(acc[mt][nt][2], acc[mt][nt][3]);
            }
    }
    __syncthreads();

    for (int g = tid; g < 2048; g += 256) {
        int row = g >> 4;
        int lc  = (g & 15) * 8;
        const float* st = stage + (size_t)row * 132 + lc;
        int orow = bm + row;
        int ncol = bn + lc;
        float v[8];
#pragma unroll
        for (int j = 0; j < 8; j++) {
            float x = st[j];
            if (EPI == 0) x += bias[ncol + j];
            if (EPI == 1) x += bias[orow];
            if (EPI == 2) x = __fdividef(1.f, 1.f + __expf(-x));
            v[j] = x;
        }
        size_t dsto = (size_t)b * sCb + (size_t)orow * pitchC + ncol;
        if (EPI == 3 || EPI == 4) {
            float* dst = (float*)Cout + dsto;
            *(float4*)dst       = make_float4(v[0], v[1], v[2], v[3]);
            *(float4*)(dst + 4) = make_float4(v[4], v[5], v[6], v[7]);
        } else if (EPI == 2) {
            uint16_t hb[8];
#pragma unroll
            for (int j = 0; j < 8; j++) {
                __half h = __float2half(v[j]);
                hb[j] = *(uint16_t*)&h;
            }
            *(uint4*)((__half*)Cout + dsto) = *(uint4*)hb;
        } else if (EPI == 1) {
            uint16_t hb[8], lb[8];
#pragma unroll
            for (int j = 0; j < 8; j++) {
                __half h = __float2half(v[j]);
                __half lo = __float2half(v[j] - __half2float(h));
                hb[j] = *(uint16_t*)&h;
                lb[j] = *(uint16_t*)&lo;
            }
            *(uint4*)((__half*)Cout + dsto) = *(uint4*)hb;
            *(uint4*)((__half*)Caux + dsto) = *(uint4*)lb;
        } else {
            uint16_t hb[8], lb[8];
#pragma unroll
            for (int j = 0; j < 8; j++) {
                __nv_bfloat16 h = __float2bfloat16(v[j]);
                __nv_bfloat16 lo = __float2bfloat16(v[j] - __bfloat162float(h));
                hb[j] = *(uint16_t*)&h;
                lb[j] = *(uint16_t*)&lo;
            }
            *(uint4*)((__nv_bfloat16*)Cout + dsto) = *(uint4*)hb;
            *(uint4*)((__nv_bfloat16*)Caux + dsto) = *(uint4*)lb;
        }
    }

    // ---- partial pooling (bmm only): each of 128 rows reduced over 128 cols
    if (EPI == 4) {
        if (tid < 128) {
            const float* sr = stage + (size_t)tid * 132;
            float s = 0.f, m = -FLT_MAX;
#pragma unroll 16
            for (int j = 0; j < 128; j++) {
                float x = sr[j];
                s += x;
                m = fmaxf(m, x);
            }
            // SWAP: blockIdx.y is the n-block
            int idx = ((b * NBLK + (int)blockIdx.y) * CCH) + bm + tid;
            float* psum = (float*)Caux;
            psum[idx]                          = s;
            psum[BATCH * NBLK * CCH + idx]     = m;
        }
    }
}

// ===========================================================================
// Prep kernels
// ===========================================================================
__global__ __launch_bounds__(256)
void transpose_split(const float* __restrict__ src,
                     __nv_bfloat16* __restrict__ dhi, __nv_bfloat16* __restrict__ dlo)
{
    __shared__ float t[32][33];
    const int b = blockIdx.z;
    const int n0 = blockIdx.x * 32, c0 = blockIdx.y * 32;
    const float* s = src + (size_t)b * CCH * NPIX;
    const int tx = threadIdx.x, ty = threadIdx.y;      // (32, 8)
#pragma unroll
    for (int j = 0; j < 32; j += 8)
        t[ty + j][tx] = s[(size_t)(c0 + ty + j) * NPIX + n0 + tx];
    __syncthreads();
    const size_t base = (size_t)b * NPIX * CCH;
#pragma unroll
    for (int j = 0; j < 32; j += 8) {
        float v = t[tx][ty + j];
        __nv_bfloat16 h = __float2bfloat16(v);
        __nv_bfloat16 l = __float2bfloat16(v - __bfloat162float(h));
        size_t off = base + (size_t)(n0 + ty + j) * CCH + c0 + tx;
        dhi[off] = h; dlo[off] = l;
    }
}

__global__ __launch_bounds__(256)
void transpose_half(const float* __restrict__ src, __half* __restrict__ dst)
{
    __shared__ float t[32][33];
    const int b = blockIdx.z;
    const int n0 = blockIdx.x * 32, c0 = blockIdx.y * 32;
    const float* s = src + (size_t)b * CCH * NPIX;
    const int tx = threadIdx.x, ty = threadIdx.y;      // (32, 8)
#pragma unroll
    for (int j = 0; j < 32; j += 8)
        t[ty + j][tx] = s[(size_t)(c0 + ty + j) * NPIX + n0 + tx];
    __syncthreads();
    const size_t base = (size_t)b * NPIX * CCH;
#pragma unroll
    for (int j = 0; j < 32; j += 8)
        dst[base + (size_t)(n0 + ty + j) * CCH + c0 + tx] = __float2half(t[tx][ty + j]);
}

__global__ __launch_bounds__(256)
void prep_wqk(const float* __restrict__ Wq, const float* __restrict__ bq,
              const float* __restrict__ Wk, const float* __restrict__ bk,
              __nv_bfloat16* __restrict__ whi, __nv_bfloat16* __restrict__ wlo,
              float* __restrict__ bqk)
{
    int i = blockIdx.x * 256 + threadIdx.x;
    float v = (i < DCH * CCH) ? Wq[i] : Wk[i - DCH * CCH];
    __nv_bfloat16 h = __float2bfloat16(v);
    whi[i] = h; wlo[i] = __float2bfloat16(v - __bfloat162float(h));
    if (i < 2 * DCH) bqk[i] = (i < DCH) ? bq[i] : bk[i - DCH];
}

__global__ __launch_bounds__(256)
void prep_wv(const float* __restrict__ Wv,
             __half* __restrict__ whi, __half* __restrict__ wlo)
{
    int i = blockIdx.x * 256 + threadIdx.x;
    float v = Wv[i];
    __half h = __float2half(v);
    whi[i] = h; wlo[i] = __float2half(v - __half2float(h));
}

// ===========================================================================
// Gate: fold 32-way partial-pool reduction + CBAM MLP + sigmoid
// ===========================================================================
__global__ __launch_bounds__(256)
void gate_kernel(const float* __restrict__ ppool,
                 const float* __restrict__ Wca1, const float* __restrict__ Wca2,
                 float* __restrict__ gate)
{
    const int b = blockIdx.x;
    const int tid = threadIdx.x;
    __shared__ float avg_s[CCH], max_s[CCH], h[RCH];

    const float* psum = ppool + (size_t)b * NBLK * CCH;
    const float* pmax = ppool + (size_t)BATCH * NBLK * CCH + (size_t)b * NBLK * CCH;
    for (int c = tid; c < CCH; c += 256) {
        float s = 0.f, m = -FLT_MAX;
#pragma unroll 8
        for (int p = 0; p < NBLK; p++) {
            s += psum[(size_t)p * CCH + c];
            m = fmaxf(m, pmax[(size_t)p * CCH + c]);
        }
        avg_s[c] = s * (1.f / NPIX);
        max_s[c] = m;
    }
    __syncthreads();

    for (int r = tid; r < RCH; r += 256) {
        float s1 = 0.f, s2 = 0.f;
        const float* w = Wca1 + (size_t)r * CCH;
        for (int c = 0; c < CCH; c++) { s1 += w[c] * avg_s[c]; s2 += w[c] * max_s[c]; }
        h[r] = fmaxf(s1, 0.f) + fmaxf(s2, 0.f);
    }
    __syncthreads();

    for (int c = tid; c < CCH; c += 256) {
        float g = 0.f;
        const float* w = Wca2 + (size_t)c * RCH;
#pragma unroll 8
        for (int r = 0; r < RCH; r++) g += w[r] * h[r];
        gate[b * CCH + c] = 1.f / (1.f + expf(-g));
    }
}

__global__ __launch_bounds__(256)
void scale_kernel(const float* __restrict__ outpre, const float* __restrict__ gate,
                  float* __restrict__ out)
{
    size_t i = (size_t)blockIdx.x * 256 + threadIdx.x;
    int row = (int)(i >> 10);
    float g = gate[row];
    float4 v = ((const float4*)outpre)[i];
    v.x *= g; v.y *= g; v.z *= g; v.w *= g;
    ((float4*)out)[i] = v;
}

// ===========================================================================
// Host launcher.  Inputs: x, x1, Wq, bq, Wk, bk, Wv, bv, Wca1, Wca2
// ===========================================================================
extern "C" void kernel_launch(void* const* d_in, const int* in_sizes, int n_in,
                              void* d_out, int out_size)
{
    const float* x    = (const float*)d_in[0];
    const float* x1   = (const float*)d_in[1];
    const float* Wq   = (const float*)d_in[2];
    const float* bq   = (const float*)d_in[3];
    const float* Wk   = (const float*)d_in[4];
    const float* bk   = (const float*)d_in[5];
    const float* Wv   = (const float*)d_in[6];
    const float* bv   = (const float*)d_in[7];
    const float* Wca1 = (const float*)d_in[8];
    const float* Wca2 = (const float*)d_in[9];
    float* out = (float*)d_out;

    constexpr int SM0 = StageCfg<0>::BYTES * 2;   // 131072
    constexpr int SM1 = StageCfg<1>::BYTES * 2;   //  98304

    static cudaStream_t s1 = nullptr;
    static cudaEvent_t evF = nullptr, evJ = nullptr;
    static bool init_done = false;
    if (!init_done) {
        cudaFuncSetAttribute(mma_gemm<1024, 0, false, 0>, cudaFuncAttributeMaxDynamicSharedMemorySize, SM0);
        cudaFuncSetAttribute(mma_gemm<1024, 1, false, 1>, cudaFuncAttributeMaxDynamicSharedMemorySize, SM1);
        cudaFuncSetAttribute(mma_gemm<128,  2, false, 0>, cudaFuncAttributeMaxDynamicSharedMemorySize, SM0);
        cudaFuncSetAttribute(mma_gemm<4096, 4, true,  1>, cudaFuncAttributeMaxDynamicSharedMemorySize, SM1);
        cudaStreamCreateWithFlags(&s1, cudaStreamNonBlocking);
        cudaEventCreateWithFlags(&evF, cudaEventDisableTiming);
        cudaEventCreateWithFlags(&evJ, cudaEventDisableTiming);
        init_done = true;
    }

    void *pxh,*pxl,*p1t,*pwh,*pwl,*pbqk,*pvh,*pvl,*pqh,*pql,*pVh,*pVl,*pat,*pop,*ppp,*pgate;
    cudaGetSymbolAddress(&pxh, g_xThi);  cudaGetSymbolAddress(&pxl, g_xTlo);
    cudaGetSymbolAddress(&p1t, g_x1T);
    cudaGetSymbolAddress(&pwh, g_Wqkhi); cudaGetSymbolAddress(&pwl, g_Wqklo);
    cudaGetSymbolAddress(&pbqk, g_bqk);
    cudaGetSymbolAddress(&pvh, g_Wvhi16); cudaGetSymbolAddress(&pvl, g_Wvlo16);
    cudaGetSymbolAddress(&pqh, g_QKThi); cudaGetSymbolAddress(&pql, g_QKTlo);
    cudaGetSymbolAddress(&pVh, g_Vhi16); cudaGetSymbolAddress(&pVl, g_Vlo16);
    cudaGetSymbolAddress(&pat, g_att16);
    cudaGetSymbolAddress(&pop, g_outpre);
    cudaGetSymbolAddress(&ppp, g_ppool); cudaGetSymbolAddress(&pgate, g_gate);

    dim3 thr(256);
    dim3 tthr(32, 8);

    const long long sXT = (long long)NPIX * CCH;
    const long long sQK = (long long)NPIX * 2 * DCH;
    const long long sV  = (long long)CCH * NPIX;
    const long long sAT = (long long)NPIX * NPIX;

    // ---- fork: V chain on s1 (depends only on x1 / Wv inputs)
    cudaEventRecord(evF, 0);
    cudaStreamWaitEvent(s1, evF, 0);

    transpose_half<<<dim3(NPIX / 32, CCH / 32, BATCH), tthr, 0, s1>>>(x1, (__half*)p1t);
    prep_wv<<<(CCH * CCH) / 256, thr, 0, s1>>>(Wv, (__half*)pvh, (__half*)pvl);
    // V[c][m] = Wv @ x1 + bv   (M=1024, N=4096, K=1024)  fp16 2-term
    mma_gemm<1024, 1, false, 1><<<dim3(32, 8, BATCH), thr, SM1, s1>>>(
        (const uint16_t*)pvh, (const uint16_t*)pvl, CCH, 0LL,
        (const uint16_t*)p1t, nullptr, CCH, sXT,
        bv, pVh, pVl, NPIX, sV);
    cudaEventRecord(evJ, s1);

    // ---- main stream: QK -> att chain
    transpose_split<<<dim3(NPIX / 32, CCH / 32, BATCH), tthr>>>(x, (__nv_bfloat16*)pxh, (__nv_bfloat16*)pxl);
    prep_wqk<<<(2 * DCH * CCH) / 256, thr>>>(Wq, bq, Wk, bk,
        (__nv_bfloat16*)pwh, (__nv_bfloat16*)pwl, (float*)pbqk);

    // QKT[n][0:256] = xT @ Wqk^T + bqk   (M=4096, N=256, K=1024)  bf16 3-term
    mma_gemm<1024, 0, false, 0><<<dim3(2, 32, BATCH), thr, SM0>>>(
        (const uint16_t*)pxh, (const uint16_t*)pxl, CCH, sXT,
        (const uint16_t*)pwh, (const uint16_t*)pwl, CCH, 0LL,
        (const float*)pbqk, pqh, pql, 2 * DCH, sQK);

    // att[n][m] = sigmoid(Q_n . K_m)     (M=4096, N=4096, K=128)  bf16 3-term
    mma_gemm<128, 2, false, 0><<<dim3(32, 32, BATCH), thr, SM0>>>(
        (const uint16_t*)pqh,       (const uint16_t*)pql,       2 * DCH, sQK,
        (const uint16_t*)pqh + DCH, (const uint16_t*)pql + DCH, 2 * DCH, sQK,
        nullptr, pat, nullptr, NPIX, sAT);

    // ---- join: bmm needs both V and att
    cudaStreamWaitEvent(0, evJ, 0);

    // outpre[c][n] = sum_m V[c][m] att[n][m]  (M=1024, N=4096, K=4096)
    // fp16 2-term; SWAP raster; fused partial pooling into epilogue.
    mma_gemm<4096, 4, true, 1><<<dim3(8, 32, BATCH), thr, SM1>>>(
        (const uint16_t*)pVh, (const uint16_t*)pVl, NPIX, sV,
        (const uint16_t*)pat, nullptr, NPIX, sAT,
        nullptr, pop, ppp, NPIX, sV);

    // tail: gate (folds partial reduction) then broadcast scale
    gate_kernel<<<BATCH, thr>>>((const float*)ppp, Wca1, Wca2, (float*)pgate);
    scale_kernel<<<(int)(((size_t)BATCH * CCH * NPIX / 4) / 256), thr>>>(
        (const float*)pop, (const float*)pgate, out);
}

// round 12
// speedup vs baseline: 6.7690x; 1.0637x over previous
#include <cuda_runtime.h>
#include <cuda_bf16.h>
#include <cuda_fp16.h>
#include <math.h>
#include <stdint.h>
#include <float.h>

#define BATCH 4
#define CCH   1024
#define DCH   128
#define RCH   64
#define NPIX  4096
#define NBLK  32              // N-blocks in the bmm (4096/128)

// ===========================================================================
// Scratch (device globals — allocation-free)
// ===========================================================================
__device__ __nv_bfloat16 g_xThi [(size_t)BATCH * NPIX * CCH];   // x^T  [b][n][c] bf16 hi
__device__ __nv_bfloat16 g_xTlo [(size_t)BATCH * NPIX * CCH];
__device__ __half        g_x1T  [(size_t)BATCH * NPIX * CCH];   // x1^T [b][n][c] fp16 single
__device__ __nv_bfloat16 g_Wqkhi[(size_t)2 * DCH * CCH];        // [256][1024]
__device__ __nv_bfloat16 g_Wqklo[(size_t)2 * DCH * CCH];
__device__ float         g_bqk[2 * DCH];
__device__ __half g_Wvhi16[(size_t)CCH * CCH];                  // Wv fp16 hi
__device__ __half g_Wvlo16[(size_t)CCH * CCH];                  // Wv fp16 lo
__device__ __nv_bfloat16 g_QKThi[(size_t)BATCH * NPIX * 2 * DCH]; // [b][n][256]
__device__ __nv_bfloat16 g_QKTlo[(size_t)BATCH * NPIX * 2 * DCH];
__device__ __half g_Vhi16[(size_t)BATCH * CCH * NPIX];          // [b][c][m] fp16 hi
__device__ __half g_Vlo16[(size_t)BATCH * CCH * NPIX];          // fp16 lo
__device__ __half g_att16[(size_t)BATCH * NPIX * NPIX];         // [b][n][m] fp16
__device__ float g_outpre[(size_t)BATCH * CCH * NPIX];          // [b][c][n] fp32
__device__ float g_ppool[2 * BATCH * NBLK * CCH];               // partial sums | partial maxes
__device__ float g_gate[BATCH * CCH];

// ===========================================================================
// Baseline-PTX helpers (mma.sync / ldmatrix / cp.async only)
// ===========================================================================
__device__ __forceinline__ uint32_t smem_u32(const void* p) {
    uint32_t a;
    asm("{ .reg .u64 t; cvta.to.shared.u64 t, %1; cvt.u32.u64 %0, t; }" : "=r"(a) : "l"(p));
    return a;
}
#define SWZ128(x) ((x) ^ (((x) >> 3) & 0x70))

__device__ __forceinline__ void cpa16(uint32_t s, const void* g) {
    asm volatile("cp.async.cg.shared.global [%0], [%1], 16;" :: "r"(s), "l"(g));
}
#define CP_COMMIT() asm volatile("cp.async.commit_group;" ::: "memory")
#define CP_WAIT0()  asm volatile("cp.async.wait_group 0;"  ::: "memory")

__device__ __forceinline__ void ldm4(uint32_t* r, uint32_t a) {
    asm volatile("ldmatrix.sync.aligned.m8n8.x4.shared.b16 {%0,%1,%2,%3}, [%4];"
        : "=r"(r[0]), "=r"(r[1]), "=r"(r[2]), "=r"(r[3]) : "r"(a));
}
__device__ __forceinline__ void mma_bf(float* d, const uint32_t* a, const uint32_t* b) {
    asm volatile("mma.sync.aligned.m16n8k16.row.col.f32.bf16.bf16.f32 "
        "{%0,%1,%2,%3}, {%4,%5,%6,%7}, {%8,%9}, {%0,%1,%2,%3};"
        : "+f"(d[0]), "+f"(d[1]), "+f"(d[2]), "+f"(d[3])
        : "r"(a[0]), "r"(a[1]), "r"(a[2]), "r"(a[3]), "r"(b[0]), "r"(b[1]));
}
__device__ __forceinline__ void mma_fp(float* d, const uint32_t* a, const uint32_t* b) {
    asm volatile("mma.sync.aligned.m16n8k16.row.col.f32.f16.f16.f32 "
        "{%0,%1,%2,%3}, {%4,%5,%6,%7}, {%8,%9}, {%0,%1,%2,%3};"
        : "+f"(d[0]), "+f"(d[1]), "+f"(d[2]), "+f"(d[3])
        : "r"(a[0]), "r"(a[1]), "r"(a[2]), "r"(a[3]), "r"(b[0]), "r"(b[1]));
}

// ===========================================================================
// Tiled MMA GEMM.  CTA tile 128x128, KC=64 (128B SW128 rows), 2-stage cp.async.
// MODE 0: bf16 3-term (A hi/lo, B hi/lo)     stage = 4 x 16KB, 1 CTA/SM
// MODE 1: fp16 2-term (A hi/lo, B single)    stage = 3 x 16KB, 2 CTAs/SM
// EPI: 0 = bias[col] + bf16 split store      1 = bias[row] + fp16 split store
//      2 = sigmoid + fp16 single store       3 = plain fp32 store
//      4 = fp32 store + per-CTA partial row pooling (sum & max over 128 cols)
// SWAP: blockIdx.x indexes M (L2-friendly rasterization for the bmm)
// ===========================================================================
#define KC 64

template<int MODE> struct StageCfg {
    static constexpr int NOPS  = (MODE == 0) ? 4 : 3;
    static constexpr int BYTES = NOPS * 16384;
};

template<int MODE>
__device__ __forceinline__ void ld_stage(uint32_t sb, int s,
    const uint16_t* __restrict__ Ahi, const uint16_t* __restrict__ Alo, int pitchA,
    const uint16_t* __restrict__ Bhi, const uint16_t* __restrict__ Blo, int pitchB,
    int k0, int tid)
{
    const uint32_t base = sb + s * StageCfg<MODE>::BYTES;
#pragma unroll
    for (int t = 0; t < 4; t++) {
        int i = tid + t * 256;                  // 0..1023
        int row = i >> 3;
        int ch  = (i & 7) * 16;                 // byte offset within 128B row
        uint32_t so = SWZ128((uint32_t)(row * 128 + ch));
        cpa16(base + so,         (const char*)(Ahi + (size_t)row * pitchA + k0) + ch);
        cpa16(base + 16384 + so, (const char*)(Alo + (size_t)row * pitchA + k0) + ch);
        cpa16(base + 32768 + so, (const char*)(Bhi + (size_t)row * pitchB + k0) + ch);
        if (MODE == 0)
            cpa16(base + 49152 + so, (const char*)(Blo + (size_t)row * pitchB + k0) + ch);
    }
}

template<int KDIM, int EPI, bool SWAP, int MODE>
__global__ __launch_bounds__(256, (MODE == 1) ? 2 : 1)
void mma_gemm(const uint16_t* __restrict__ Ahi, const uint16_t* __restrict__ Alo,
              int pitchA, long long sAb,
              const uint16_t* __restrict__ Bhi, const uint16_t* __restrict__ Blo,
              int pitchB, long long sBb,
              const float* __restrict__ bias,
              void* __restrict__ Cout, void* __restrict__ Caux,
              int pitchC, long long sCb)
{
    extern __shared__ char smem[];
    const uint32_t sb = smem_u32(smem);
    const int tid = threadIdx.x;
    const int bm = (SWAP ? blockIdx.x : blockIdx.y) * 128;
    const int bn = (SWAP ? blockIdx.y : blockIdx.x) * 128;
    const int b  = blockIdx.z;

    Ahi += (size_t)b * sAb + (size_t)bm * pitchA;
    Alo += (size_t)b * sAb + (size_t)bm * pitchA;
    Bhi += (size_t)b * sBb + (size_t)bn * pitchB;
    if (MODE == 0) Blo += (size_t)b * sBb + (size_t)bn * pitchB;

    constexpr int NC = KDIM / KC;
    constexpr int SBYTES = StageCfg<MODE>::BYTES;

    // 8 warps = 4(M) x 2(N); warp tile 32(M) x 64(N)
    const int w  = tid >> 5, l = tid & 31;
    const int wm = (w & 3) * 32;
    const int wn = (w >> 2) * 64;

    const int a_row  = l & 15;
    const int a_kb   = (l >> 4) * 16;
    const int b_noff = ((l >> 4) & 1) * 8 + (l & 7);
    const int b_kb   = ((l >> 3) & 1) * 16;

    float acc[2][8][4];
#pragma unroll
    for (int i = 0; i < 2; i++)
#pragma unroll
        for (int j = 0; j < 8; j++)
#pragma unroll
            for (int q = 0; q < 4; q++) acc[i][j][q] = 0.f;

    ld_stage<MODE>(sb, 0, Ahi, Alo, pitchA, Bhi, Blo, pitchB, 0, tid);
    CP_COMMIT();

    int buf = 0;
#pragma unroll 1
    for (int c = 0; c < NC; c++) {
        CP_WAIT0();
        __syncthreads();
        if (c + 1 < NC) {
            ld_stage<MODE>(sb, buf ^ 1, Ahi, Alo, pitchA, Bhi, Blo, pitchB, (c + 1) * KC, tid);
            CP_COMMIT();
        }
        const uint32_t bAH = sb + buf * SBYTES;
        const uint32_t bAL = bAH + 16384;
        const uint32_t bBH = bAH + 32768;
        const uint32_t bBL = bAH + 49152;   // MODE 0 only

#pragma unroll
        for (int ks = 0; ks < 4; ks++) {
            const int kb = ks * 32;
            uint32_t ah[2][4], al[2][4];
#pragma unroll
            for (int mt = 0; mt < 2; mt++) {
                uint32_t off = SWZ128((uint32_t)((wm + mt * 16 + a_row) * 128 + kb + a_kb));
                ldm4(ah[mt], bAH + off);
                ldm4(al[mt], bAL + off);
            }
            uint32_t bh[8][2];
            uint32_t bl[8][2];
#pragma unroll
            for (int p = 0; p < 4; p++) {
                uint32_t off = SWZ128((uint32_t)((wn + p * 16 + b_noff) * 128 + kb + b_kb));
                uint32_t r[4];
                ldm4(r, bBH + off);
                bh[2 * p][0] = r[0]; bh[2 * p][1] = r[1];
                bh[2 * p + 1][0] = r[2]; bh[2 * p + 1][1] = r[3];
                if (MODE == 0) {
                    ldm4(r, bBL + off);
                    bl[2 * p][0] = r[0]; bl[2 * p][1] = r[1];
                    bl[2 * p + 1][0] = r[2]; bl[2 * p + 1][1] = r[3];
                }
            }
#pragma unroll
            for (int mt = 0; mt < 2; mt++)
#pragma unroll
                for (int nt = 0; nt < 8; nt++) {
                    if (MODE == 0) {
                        mma_bf(acc[mt][nt], ah[mt], bh[nt]);   // hi*hi
                        mma_bf(acc[mt][nt], ah[mt], bl[nt]);   // hi*lo
                        mma_bf(acc[mt][nt], al[mt], bh[nt]);   // lo*hi
                    } else {
                        mma_fp(acc[mt][nt], ah[mt], bh[nt]);   // hi*B
                        mma_fp(acc[mt][nt], al[mt], bh[nt]);   // lo*B
                    }
                }
        }
        buf ^= 1;
    }
    __syncthreads();   // operand SMEM now reusable as staging

    // ---- epilogue: regs -> SMEM stage (fp32, pitch 132) -> coalesced GMEM
    float* stage = (float*)smem;
    {
        const int qr = l >> 2, qc = (l & 3) * 2;
#pragma unroll
        for (int mt = 0; mt < 2; mt++)
#pragma unroll
            for (int nt = 0; nt < 8; nt++) {
                int r0 = wm + mt * 16 + qr;
                int c0 = wn + nt * 8 + qc;
                *(float2*)&stage[(size_t)r0 * 132 + c0] =
                    make_float2(acc[mt][nt][0], acc[mt][nt][1]);
                *(float2*)&stage[(size_t)(r0 + 8) * 132 + c0] =
                    make_float2(acc[mt][nt][2], acc[mt][nt][3]);
            }
    }
    __syncthreads();

    for (int g = tid; g < 2048; g += 256) {
        int row = g >> 4;
        int lc  = (g & 15) * 8;
        const float* st = stage + (size_t)row * 132 + lc;
        int orow = bm + row;
        int ncol = bn + lc;
        float v[8];
#pragma unroll
        for (int j = 0; j < 8; j++) {
            float x = st[j];
            if (EPI == 0) x += bias[ncol + j];
            if (EPI == 1) x += bias[orow];
            if (EPI == 2) x = __fdividef(1.f, 1.f + __expf(-x));
            v[j] = x;
        }
        size_t dsto = (size_t)b * sCb + (size_t)orow * pitchC + ncol;
        if (EPI == 3 || EPI == 4) {
            float* dst = (float*)Cout + dsto;
            *(float4*)dst       = make_float4(v[0], v[1], v[2], v[3]);
            *(float4*)(dst + 4) = make_float4(v[4], v[5], v[6], v[7]);
        } else if (EPI == 2) {
            uint16_t hb[8];
#pragma unroll
            for (int j = 0; j < 8; j++) {
                __half h = __float2half(v[j]);
                hb[j] = *(uint16_t*)&h;
            }
            *(uint4*)((__half*)Cout + dsto) = *(uint4*)hb;
        } else if (EPI == 1) {
            uint16_t hb[8], lb[8];
#pragma unroll
            for (int j = 0; j < 8; j++) {
                __half h = __float2half(v[j]);
                __half lo = __float2half(v[j] - __half2float(h));
                hb[j] = *(uint16_t*)&h;
                lb[j] = *(uint16_t*)&lo;
            }
            *(uint4*)((__half*)Cout + dsto) = *(uint4*)hb;
            *(uint4*)((__half*)Caux + dsto) = *(uint4*)lb;
        } else {
            uint16_t hb[8], lb[8];
#pragma unroll
            for (int j = 0; j < 8; j++) {
                __nv_bfloat16 h = __float2bfloat16(v[j]);
                __nv_bfloat16 lo = __float2bfloat16(v[j] - __bfloat162float(h));
                hb[j] = *(uint16_t*)&h;
                lb[j] = *(uint16_t*)&lo;
            }
            *(uint4*)((__nv_bfloat16*)Cout + dsto) = *(uint4*)hb;
            *(uint4*)((__nv_bfloat16*)Caux + dsto) = *(uint4*)lb;
        }
    }

    // ---- partial pooling (bmm only): each of 128 rows reduced over 128 cols
    if (EPI == 4) {
        if (tid < 128) {
            const float* sr = stage + (size_t)tid * 132;
            float s = 0.f, m = -FLT_MAX;
#pragma unroll 16
            for (int j = 0; j < 128; j++) {
                float x = sr[j];
                s += x;
                m = fmaxf(m, x);
            }
            // SWAP: blockIdx.y is the n-block
            int idx = ((b * NBLK + (int)blockIdx.y) * CCH) + bm + tid;
            float* psum = (float*)Caux;
            psum[idx]                          = s;
            psum[BATCH * NBLK * CCH + idx]     = m;
        }
    }
}

// ===========================================================================
// Prep kernels
// ===========================================================================
__global__ __launch_bounds__(256)
void transpose_split(const float* __restrict__ src,
                     __nv_bfloat16* __restrict__ dhi, __nv_bfloat16* __restrict__ dlo)
{
    __shared__ float t[32][33];
    const int b = blockIdx.z;
    const int n0 = blockIdx.x * 32, c0 = blockIdx.y * 32;
    const float* s = src + (size_t)b * CCH * NPIX;
    const int tx = threadIdx.x, ty = threadIdx.y;      // (32, 8)
#pragma unroll
    for (int j = 0; j < 32; j += 8)
        t[ty + j][tx] = s[(size_t)(c0 + ty + j) * NPIX + n0 + tx];
    __syncthreads();
    const size_t base = (size_t)b * NPIX * CCH;
#pragma unroll
    for (int j = 0; j < 32; j += 8) {
        float v = t[tx][ty + j];
        __nv_bfloat16 h = __float2bfloat16(v);
        __nv_bfloat16 l = __float2bfloat16(v - __bfloat162float(h));
        size_t off = base + (size_t)(n0 + ty + j) * CCH + c0 + tx;
        dhi[off] = h; dlo[off] = l;
    }
}

__global__ __launch_bounds__(256)
void transpose_half(const float* __restrict__ src, __half* __restrict__ dst)
{
    __shared__ float t[32][33];
    const int b = blockIdx.z;
    const int n0 = blockIdx.x * 32, c0 = blockIdx.y * 32;
    const float* s = src + (size_t)b * CCH * NPIX;
    const int tx = threadIdx.x, ty = threadIdx.y;      // (32, 8)
#pragma unroll
    for (int j = 0; j < 32; j += 8)
        t[ty + j][tx] = s[(size_t)(c0 + ty + j) * NPIX + n0 + tx];
    __syncthreads();
    const size_t base = (size_t)b * NPIX * CCH;
#pragma unroll
    for (int j = 0; j < 32; j += 8)
        dst[base + (size_t)(n0 + ty + j) * CCH + c0 + tx] = __float2half(t[tx][ty + j]);
}

__global__ __launch_bounds__(256)
void prep_wqk(const float* __restrict__ Wq, const float* __restrict__ bq,
              const float* __restrict__ Wk, const float* __restrict__ bk,
              __nv_bfloat16* __restrict__ whi, __nv_bfloat16* __restrict__ wlo,
              float* __restrict__ bqk)
{
    int i = blockIdx.x * 256 + threadIdx.x;
    float v = (i < DCH * CCH) ? Wq[i] : Wk[i - DCH * CCH];
    __nv_bfloat16 h = __float2bfloat16(v);
    whi[i] = h; wlo[i] = __float2bfloat16(v - __bfloat162float(h));
    if (i < 2 * DCH) bqk[i] = (i < DCH) ? bq[i] : bk[i - DCH];
}

__global__ __launch_bounds__(256)
void prep_wv(const float* __restrict__ Wv,
             __half* __restrict__ whi, __half* __restrict__ wlo)
{
    int i = blockIdx.x * 256 + threadIdx.x;
    float v = Wv[i];
    __half h = __float2half(v);
    whi[i] = h; wlo[i] = __float2half(v - __half2float(h));
}

// ===========================================================================
// Gate: fold 32-way partial-pool reduction + CBAM MLP + sigmoid
// ===========================================================================
__global__ __launch_bounds__(256)
void gate_kernel(const float* __restrict__ ppool,
                 const float* __restrict__ Wca1, const float* __restrict__ Wca2,
                 float* __restrict__ gate)
{
    const int b = blockIdx.x;
    const int tid = threadIdx.x;
    __shared__ float avg_s[CCH], max_s[CCH], h[RCH];

    const float* psum = ppool + (size_t)b * NBLK * CCH;
    const float* pmax = ppool + (size_t)BATCH * NBLK * CCH + (size_t)b * NBLK * CCH;
    for (int c = tid; c < CCH; c += 256) {
        float s = 0.f, m = -FLT_MAX;
#pragma unroll 8
        for (int p = 0; p < NBLK; p++) {
            s += psum[(size_t)p * CCH + c];
            m = fmaxf(m, pmax[(size_t)p * CCH + c]);
        }
        avg_s[c] = s * (1.f / NPIX);
        max_s[c] = m;
    }
    __syncthreads();

    for (int r = tid; r < RCH; r += 256) {
        float s1 = 0.f, s2 = 0.f;
        const float* w = Wca1 + (size_t)r * CCH;
        for (int c = 0; c < CCH; c++) { s1 += w[c] * avg_s[c]; s2 += w[c] * max_s[c]; }
        h[r] = fmaxf(s1, 0.f) + fmaxf(s2, 0.f);
    }
    __syncthreads();

    for (int c = tid; c < CCH; c += 256) {
        float g = 0.f;
        const float* w = Wca2 + (size_t)c * RCH;
#pragma unroll 8
        for (int r = 0; r < RCH; r++) g += w[r] * h[r];
        gate[b * CCH + c] = 1.f / (1.f + expf(-g));
    }
}

__global__ __launch_bounds__(256)
void scale_kernel(const float* __restrict__ outpre, const float* __restrict__ gate,
                  float* __restrict__ out)
{
    size_t i = (size_t)blockIdx.x * 256 + threadIdx.x;
    int row = (int)(i >> 10);
    float g = gate[row];
    float4 v = ((const float4*)outpre)[i];
    v.x *= g; v.y *= g; v.z *= g; v.w *= g;
    ((float4*)out)[i] = v;
}

// ===========================================================================
// Host launcher.  Inputs: x, x1, Wq, bq, Wk, bk, Wv, bv, Wca1, Wca2
// ===========================================================================
extern "C" void kernel_launch(void* const* d_in, const int* in_sizes, int n_in,
                              void* d_out, int out_size)
{
    const float* x    = (const float*)d_in[0];
    const float* x1   = (const float*)d_in[1];
    const float* Wq   = (const float*)d_in[2];
    const float* bq   = (const float*)d_in[3];
    const float* Wk   = (const float*)d_in[4];
    const float* bk   = (const float*)d_in[5];
    const float* Wv   = (const float*)d_in[6];
    const float* bv   = (const float*)d_in[7];
    const float* Wca1 = (const float*)d_in[8];
    const float* Wca2 = (const float*)d_in[9];
    float* out = (float*)d_out;

    constexpr int SM0 = StageCfg<0>::BYTES * 2;   // 131072
    constexpr int SM1 = StageCfg<1>::BYTES * 2;   //  98304 (x2 CTAs = 196KB/SM)

    static cudaStream_t s1 = nullptr;
    static cudaEvent_t evF = nullptr, evJ = nullptr;
    static bool init_done = false;
    if (!init_done) {
        cudaFuncSetAttribute(mma_gemm<1024, 0, false, 0>, cudaFuncAttributeMaxDynamicSharedMemorySize, SM0);
        cudaFuncSetAttribute(mma_gemm<1024, 1, false, 1>, cudaFuncAttributeMaxDynamicSharedMemorySize, SM1);
        cudaFuncSetAttribute(mma_gemm<128,  2, false, 0>, cudaFuncAttributeMaxDynamicSharedMemorySize, SM0);
        cudaFuncSetAttribute(mma_gemm<4096, 4, true,  1>, cudaFuncAttributeMaxDynamicSharedMemorySize, SM1);
        cudaStreamCreateWithFlags(&s1, cudaStreamNonBlocking);
        cudaEventCreateWithFlags(&evF, cudaEventDisableTiming);
        cudaEventCreateWithFlags(&evJ, cudaEventDisableTiming);
        init_done = true;
    }

    void *pxh,*pxl,*p1t,*pwh,*pwl,*pbqk,*pvh,*pvl,*pqh,*pql,*pVh,*pVl,*pat,*pop,*ppp,*pgate;
    cudaGetSymbolAddress(&pxh, g_xThi);  cudaGetSymbolAddress(&pxl, g_xTlo);
    cudaGetSymbolAddress(&p1t, g_x1T);
    cudaGetSymbolAddress(&pwh, g_Wqkhi); cudaGetSymbolAddress(&pwl, g_Wqklo);
    cudaGetSymbolAddress(&pbqk, g_bqk);
    cudaGetSymbolAddress(&pvh, g_Wvhi16); cudaGetSymbolAddress(&pvl, g_Wvlo16);
    cudaGetSymbolAddress(&pqh, g_QKThi); cudaGetSymbolAddress(&pql, g_QKTlo);
    cudaGetSymbolAddress(&pVh, g_Vhi16); cudaGetSymbolAddress(&pVl, g_Vlo16);
    cudaGetSymbolAddress(&pat, g_att16);
    cudaGetSymbolAddress(&pop, g_outpre);
    cudaGetSymbolAddress(&ppp, g_ppool); cudaGetSymbolAddress(&pgate, g_gate);

    dim3 thr(256);
    dim3 tthr(32, 8);

    const long long sXT = (long long)NPIX * CCH;
    const long long sQK = (long long)NPIX * 2 * DCH;
    const long long sV  = (long long)CCH * NPIX;
    const long long sAT = (long long)NPIX * NPIX;

    // ---- fork: V chain on s1 (depends only on x1 / Wv inputs)
    cudaEventRecord(evF, 0);
    cudaStreamWaitEvent(s1, evF, 0);

    transpose_half<<<dim3(NPIX / 32, CCH / 32, BATCH), tthr, 0, s1>>>(x1, (__half*)p1t);
    prep_wv<<<(CCH * CCH) / 256, thr, 0, s1>>>(Wv, (__half*)pvh, (__half*)pvl);
    // V[c][m] = Wv @ x1 + bv   (M=1024, N=4096, K=1024)  fp16 2-term, 2 CTAs/SM
    mma_gemm<1024, 1, false, 1><<<dim3(32, 8, BATCH), thr, SM1, s1>>>(
        (const uint16_t*)pvh, (const uint16_t*)pvl, CCH, 0LL,
        (const uint16_t*)p1t, nullptr, CCH, sXT,
        bv, pVh, pVl, NPIX, sV);
    cudaEventRecord(evJ, s1);

    // ---- main stream: QK -> att chain
    transpose_split<<<dim3(NPIX / 32, CCH / 32, BATCH), tthr>>>(x, (__nv_bfloat16*)pxh, (__nv_bfloat16*)pxl);
    prep_wqk<<<(2 * DCH * CCH) / 256, thr>>>(Wq, bq, Wk, bk,
        (__nv_bfloat16*)pwh, (__nv_bfloat16*)pwl, (float*)pbqk);

    // QKT[n][0:256] = xT @ Wqk^T + bqk   (M=4096, N=256, K=1024)  bf16 3-term
    mma_gemm<1024, 0, false, 0><<<dim3(2, 32, BATCH), thr, SM0>>>(
        (const uint16_t*)pxh, (const uint16_t*)pxl, CCH, sXT,
        (const uint16_t*)pwh, (const uint16_t*)pwl, CCH, 0LL,
        (const float*)pbqk, pqh, pql, 2 * DCH, sQK);

    // att[n][m] = sigmoid(Q_n . K_m)     (M=4096, N=4096, K=128)  bf16 3-term
    mma_gemm<128, 2, false, 0><<<dim3(32, 32, BATCH), thr, SM0>>>(
        (const uint16_t*)pqh,       (const uint16_t*)pql,       2 * DCH, sQK,
        (const uint16_t*)pqh + DCH, (const uint16_t*)pql + DCH, 2 * DCH, sQK,
        nullptr, pat, nullptr, NPIX, sAT);

    // ---- join: bmm needs both V and att
    cudaStreamWaitEvent(0, evJ, 0);

    // outpre[c][n] = sum_m V[c][m] att[n][m]  (M=1024, N=4096, K=4096)
    // fp16 2-term, 2 CTAs/SM; SWAP raster; fused partial pooling.
    mma_gemm<4096, 4, true, 1><<<dim3(8, 32, BATCH), thr, SM1>>>(
        (const uint16_t*)pVh, (const uint16_t*)pVl, NPIX, sV,
        (const uint16_t*)pat, nullptr, NPIX, sAT,
        nullptr, pop, ppp, NPIX, sV);

    // tail: gate (folds partial reduction) then broadcast scale
    gate_kernel<<<BATCH, thr>>>((const float*)ppp, Wca1, Wca2, (float*)pgate);
    scale_kernel<<<(int)(((size_t)BATCH * CCH * NPIX / 4) / 256), thr>>>(
        (const float*)pop, (const float*)pgate, out);
}

// round 13
// speedup vs baseline: 6.8482x; 1.0117x over previous
#include <cuda_runtime.h>
#include <cuda_bf16.h>
#include <cuda_fp16.h>
#include <math.h>
#include <stdint.h>
#include <float.h>

#define BATCH 4
#define CCH   1024
#define DCH   128
#define RCH   64
#define NPIX  4096
#define NBLK  32              // N-blocks in the bmm (4096/128)

// ===========================================================================
// Scratch (device globals — allocation-free)
// ===========================================================================
__device__ __nv_bfloat16 g_xThi [(size_t)BATCH * NPIX * CCH];   // x^T  [b][n][c] bf16 hi
__device__ __nv_bfloat16 g_xTlo [(size_t)BATCH * NPIX * CCH];
__device__ __half        g_x1T  [(size_t)BATCH * NPIX * CCH];   // x1^T [b][n][c] fp16 single
__device__ __nv_bfloat16 g_Wqkhi[(size_t)2 * DCH * CCH];        // [256][1024]
__device__ __nv_bfloat16 g_Wqklo[(size_t)2 * DCH * CCH];
__device__ float         g_bqk[2 * DCH];
__device__ __half g_Wvhi16[(size_t)CCH * CCH];                  // Wv fp16 hi
__device__ __half g_Wvlo16[(size_t)CCH * CCH];                  // Wv fp16 lo
__device__ __nv_bfloat16 g_QKThi[(size_t)BATCH * NPIX * 2 * DCH]; // [b][n][256]
__device__ __nv_bfloat16 g_QKTlo[(size_t)BATCH * NPIX * 2 * DCH];
__device__ __half g_Vhi16[(size_t)BATCH * CCH * NPIX];          // [b][c][m] fp16 hi
__device__ __half g_Vlo16[(size_t)BATCH * CCH * NPIX];          // fp16 lo
__device__ __half g_att16[(size_t)BATCH * NPIX * NPIX];         // [b][n][m] fp16
__device__ float g_outpre[(size_t)BATCH * CCH * NPIX];          // [b][c][n] fp32
__device__ float g_ppool[2 * BATCH * NBLK * CCH];               // partial sums | partial maxes
__device__ float g_gate[BATCH * CCH];

// ===========================================================================
// Baseline-PTX helpers (mma.sync / ldmatrix / cp.async only)
// ===========================================================================
__device__ __forceinline__ uint32_t smem_u32(const void* p) {
    uint32_t a;
    asm("{ .reg .u64 t; cvta.to.shared.u64 t, %1; cvt.u32.u64 %0, t; }" : "=r"(a) : "l"(p));
    return a;
}
#define SWZ128(x) ((x) ^ (((x) >> 3) & 0x70))

__device__ __forceinline__ void cpa16(uint32_t s, const void* g) {
    asm volatile("cp.async.cg.shared.global [%0], [%1], 16;" :: "r"(s), "l"(g));
}
#define CP_COMMIT() asm volatile("cp.async.commit_group;" ::: "memory")
#define CP_WAIT0()  asm volatile("cp.async.wait_group 0;"  ::: "memory")

__device__ __forceinline__ void ldm4(uint32_t* r, uint32_t a) {
    asm volatile("ldmatrix.sync.aligned.m8n8.x4.shared.b16 {%0,%1,%2,%3}, [%4];"
        : "=r"(r[0]), "=r"(r[1]), "=r"(r[2]), "=r"(r[3]) : "r"(a));
}
__device__ __forceinline__ void mma_bf(float* d, const uint32_t* a, const uint32_t* b) {
    asm volatile("mma.sync.aligned.m16n8k16.row.col.f32.bf16.bf16.f32 "
        "{%0,%1,%2,%3}, {%4,%5,%6,%7}, {%8,%9}, {%0,%1,%2,%3};"
        : "+f"(d[0]), "+f"(d[1]), "+f"(d[2]), "+f"(d[3])
        : "r"(a[0]), "r"(a[1]), "r"(a[2]), "r"(a[3]), "r"(b[0]), "r"(b[1]));
}
__device__ __forceinline__ void mma_fp(float* d, const uint32_t* a, const uint32_t* b) {
    asm volatile("mma.sync.aligned.m16n8k16.row.col.f32.f16.f16.f32 "
        "{%0,%1,%2,%3}, {%4,%5,%6,%7}, {%8,%9}, {%0,%1,%2,%3};"
        : "+f"(d[0]), "+f"(d[1]), "+f"(d[2]), "+f"(d[3])
        : "r"(a[0]), "r"(a[1]), "r"(a[2]), "r"(a[3]), "r"(b[0]), "r"(b[1]));
}

// ===========================================================================
// Tiled MMA GEMM.  CTA tile 128x128, KC=64 (128B SW128 rows), cp.async stages.
// MODE 0: bf16 3-term (A hi/lo, B hi/lo)     stage = 4 x 16KB
// MODE 1: fp16 2-term (A hi/lo, B single)    stage = 3 x 16KB
// NSTAGE: 1 = single-buffer (short-K kernels, enables 2-CTA residency)
//         2 = double-buffer
// EPI: 0 = bias[col] + bf16 split store      1 = bias[row] + fp16 split store
//      2 = sigmoid + fp16 single store       3 = plain fp32 store
//      4 = fp32 store + per-CTA partial row pooling (sum & max over 128 cols)
// SWAP: blockIdx.x indexes M (L2-friendly rasterization for the bmm)
// ===========================================================================
#define KC 64

template<int MODE> struct StageCfg {
    static constexpr int NOPS  = (MODE == 0) ? 4 : 3;
    static constexpr int BYTES = NOPS * 16384;
};

template<int MODE>
__device__ __forceinline__ void ld_stage(uint32_t sb, int s,
    const uint16_t* __restrict__ Ahi, const uint16_t* __restrict__ Alo, int pitchA,
    const uint16_t* __restrict__ Bhi, const uint16_t* __restrict__ Blo, int pitchB,
    int k0, int tid)
{
    const uint32_t base = sb + s * StageCfg<MODE>::BYTES;
#pragma unroll
    for (int t = 0; t < 4; t++) {
        int i = tid + t * 256;                  // 0..1023
        int row = i >> 3;
        int ch  = (i & 7) * 16;                 // byte offset within 128B row
        uint32_t so = SWZ128((uint32_t)(row * 128 + ch));
        cpa16(base + so,         (const char*)(Ahi + (size_t)row * pitchA + k0) + ch);
        cpa16(base + 16384 + so, (const char*)(Alo + (size_t)row * pitchA + k0) + ch);
        cpa16(base + 32768 + so, (const char*)(Bhi + (size_t)row * pitchB + k0) + ch);
        if (MODE == 0)
            cpa16(base + 49152 + so, (const char*)(Blo + (size_t)row * pitchB + k0) + ch);
    }
}

// Compute one K-chunk from the given stage buffer (per-p interleaved, low-reg)
template<int MODE>
__device__ __forceinline__ void compute_chunk(uint32_t bufbase,
    int wm, int wn, int a_row, int a_kb, int b_noff, int b_kb,
    float acc[2][8][4])
{
    const uint32_t bAH = bufbase;
    const uint32_t bAL = bufbase + 16384;
    const uint32_t bBH = bufbase + 32768;
    const uint32_t bBL = bufbase + 49152;   // MODE 0 only
#pragma unroll
    for (int ks = 0; ks < 4; ks++) {
        const int kb = ks * 32;
        uint32_t ah[2][4], al[2][4];
#pragma unroll
        for (int mt = 0; mt < 2; mt++) {
            uint32_t off = SWZ128((uint32_t)((wm + mt * 16 + a_row) * 128 + kb + a_kb));
            ldm4(ah[mt], bAH + off);
            ldm4(al[mt], bAL + off);
        }
#pragma unroll
        for (int p = 0; p < 4; p++) {
            uint32_t off = SWZ128((uint32_t)((wn + p * 16 + b_noff) * 128 + kb + b_kb));
            uint32_t bhp[4];
            ldm4(bhp, bBH + off);
            if (MODE == 0) {
                uint32_t blp[4];
                ldm4(blp, bBL + off);
#pragma unroll
                for (int mt = 0; mt < 2; mt++) {
                    mma_bf(acc[mt][2 * p],     ah[mt], bhp + 0);   // hi*hi
                    mma_bf(acc[mt][2 * p],     ah[mt], blp + 0);   // hi*lo
                    mma_bf(acc[mt][2 * p],     al[mt], bhp + 0);   // lo*hi
                    mma_bf(acc[mt][2 * p + 1], ah[mt], bhp + 2);
                    mma_bf(acc[mt][2 * p + 1], ah[mt], blp + 2);
                    mma_bf(acc[mt][2 * p + 1], al[mt], bhp + 2);
                }
            } else {
#pragma unroll
                for (int mt = 0; mt < 2; mt++) {
                    mma_fp(acc[mt][2 * p],     ah[mt], bhp + 0);   // hi*B
                    mma_fp(acc[mt][2 * p],     al[mt], bhp + 0);   // lo*B
                    mma_fp(acc[mt][2 * p + 1], ah[mt], bhp + 2);
                    mma_fp(acc[mt][2 * p + 1], al[mt], bhp + 2);
                }
            }
        }
    }
}

template<int KDIM, int EPI, bool SWAP, int MODE, int NSTAGE, int OCC>
__global__ __launch_bounds__(256, OCC)
void mma_gemm(const uint16_t* __restrict__ Ahi, const uint16_t* __restrict__ Alo,
              int pitchA, long long sAb,
              const uint16_t* __restrict__ Bhi, const uint16_t* __restrict__ Blo,
              int pitchB, long long sBb,
              const float* __restrict__ bias,
              void* __restrict__ Cout, void* __restrict__ Caux,
              int pitchC, long long sCb)
{
    extern __shared__ char smem[];
    const uint32_t sb = smem_u32(smem);
    const int tid = threadIdx.x;
    const int bm = (SWAP ? blockIdx.x : blockIdx.y) * 128;
    const int bn = (SWAP ? blockIdx.y : blockIdx.x) * 128;
    const int b  = blockIdx.z;

    Ahi += (size_t)b * sAb + (size_t)bm * pitchA;
    Alo += (size_t)b * sAb + (size_t)bm * pitchA;
    Bhi += (size_t)b * sBb + (size_t)bn * pitchB;
    if (MODE == 0) Blo += (size_t)b * sBb + (size_t)bn * pitchB;

    constexpr int NC = KDIM / KC;
    constexpr int SBYTES = StageCfg<MODE>::BYTES;

    // 8 warps = 4(M) x 2(N); warp tile 32(M) x 64(N)
    const int w  = tid >> 5, l = tid & 31;
    const int wm = (w & 3) * 32;
    const int wn = (w >> 2) * 64;

    const int a_row  = l & 15;
    const int a_kb   = (l >> 4) * 16;
    const int b_noff = ((l >> 4) & 1) * 8 + (l & 7);
    const int b_kb   = ((l >> 3) & 1) * 16;

    float acc[2][8][4];
#pragma unroll
    for (int i = 0; i < 2; i++)
#pragma unroll
        for (int j = 0; j < 8; j++)
#pragma unroll
            for (int q = 0; q < 4; q++) acc[i][j][q] = 0.f;

    if (NSTAGE == 2) {
        ld_stage<MODE>(sb, 0, Ahi, Alo, pitchA, Bhi, Blo, pitchB, 0, tid);
        CP_COMMIT();
        int buf = 0;
#pragma unroll 1
        for (int c = 0; c < NC; c++) {
            CP_WAIT0();
            __syncthreads();
            if (c + 1 < NC) {
                ld_stage<MODE>(sb, buf ^ 1, Ahi, Alo, pitchA, Bhi, Blo, pitchB, (c + 1) * KC, tid);
                CP_COMMIT();
            }
            compute_chunk<MODE>(sb + buf * SBYTES, wm, wn, a_row, a_kb, b_noff, b_kb, acc);
            buf ^= 1;
        }
    } else {
#pragma unroll 1
        for (int c = 0; c < NC; c++) {
            ld_stage<MODE>(sb, 0, Ahi, Alo, pitchA, Bhi, Blo, pitchB, c * KC, tid);
            CP_COMMIT();
            CP_WAIT0();
            __syncthreads();
            compute_chunk<MODE>(sb, wm, wn, a_row, a_kb, b_noff, b_kb, acc);
            __syncthreads();   // all reads done before next overwrite
        }
    }
    __syncthreads();   // operand SMEM now reusable as staging

    // ---- epilogue: regs -> SMEM stage (fp32, pitch 132) -> coalesced GMEM
    float* stage = (float*)smem;
    {
        const int qr = l >> 2, qc = (l & 3) * 2;
#pragma unroll
        for (int mt = 0; mt < 2; mt++)
#pragma unroll
            for (int nt = 0; nt < 8; nt++) {
                int r0 = wm + mt * 16 + qr;
                int c0 = wn + nt * 8 + qc;
                *(float2*)&stage[(size_t)r0 * 132 + c0] =
                    make_float2(acc[mt][nt][0], acc[mt][nt][1]);
                *(float2*)&stage[(size_t)(r0 + 8) * 132 + c0] =
                    make_float2(acc[mt][nt][2], acc[mt][nt][3]);
            }
    }
    __syncthreads();

    for (int g = tid; g < 2048; g += 256) {
        int row = g >> 4;
        int lc  = (g & 15) * 8;
        const float* st = stage + (size_t)row * 132 + lc;
        int orow = bm + row;
        int ncol = bn + lc;
        float v[8];
#pragma unroll
        for (int j = 0; j < 8; j++) {
            float x = st[j];
            if (EPI == 0) x += bias[ncol + j];
            if (EPI == 1) x += bias[orow];
            if (EPI == 2) x = __fdividef(1.f, 1.f + __expf(-x));
            v[j] = x;
        }
        size_t dsto = (size_t)b * sCb + (size_t)orow * pitchC + ncol;
        if (EPI == 3 || EPI == 4) {
            float* dst = (float*)Cout + dsto;
            *(float4*)dst       = make_float4(v[0], v[1], v[2], v[3]);
            *(float4*)(dst + 4) = make_float4(v[4], v[5], v[6], v[7]);
        } else if (EPI == 2) {
            uint16_t hb[8];
#pragma unroll
            for (int j = 0; j < 8; j++) {
                __half h = __float2half(v[j]);
                hb[j] = *(uint16_t*)&h;
            }
            *(uint4*)((__half*)Cout + dsto) = *(uint4*)hb;
        } else if (EPI == 1) {
            uint16_t hb[8], lb[8];
#pragma unroll
            for (int j = 0; j < 8; j++) {
                __half h = __float2half(v[j]);
                __half lo = __float2half(v[j] - __half2float(h));
                hb[j] = *(uint16_t*)&h;
                lb[j] = *(uint16_t*)&lo;
            }
            *(uint4*)((__half*)Cout + dsto) = *(uint4*)hb;
            *(uint4*)((__half*)Caux + dsto) = *(uint4*)lb;
        } else {
            uint16_t hb[8], lb[8];
#pragma unroll
            for (int j = 0; j < 8; j++) {
                __nv_bfloat16 h = __float2bfloat16(v[j]);
                __nv_bfloat16 lo = __float2bfloat16(v[j] - __bfloat162float(h));
                hb[j] = *(uint16_t*)&h;
                lb[j] = *(uint16_t*)&lo;
            }
            *(uint4*)((__nv_bfloat16*)Cout + dsto) = *(uint4*)hb;
            *(uint4*)((__nv_bfloat16*)Caux + dsto) = *(uint4*)lb;
        }
    }

    // ---- partial pooling (bmm only): each of 128 rows reduced over 128 cols
    if (EPI == 4) {
        if (tid < 128) {
            const float* sr = stage + (size_t)tid * 132;
            float s = 0.f, m = -FLT_MAX;
#pragma unroll 16
            for (int j = 0; j < 128; j++) {
                float x = sr[j];
                s += x;
                m = fmaxf(m, x);
            }
            // SWAP: blockIdx.y is the n-block
            int idx = ((b * NBLK + (int)blockIdx.y) * CCH) + bm + tid;
            float* psum = (float*)Caux;
            psum[idx]                          = s;
            psum[BATCH * NBLK * CCH + idx]     = m;
        }
    }
}

// ===========================================================================
// Prep kernels
// ===========================================================================
__global__ __launch_bounds__(256)
void transpose_split(const float* __restrict__ src,
                     __nv_bfloat16* __restrict__ dhi, __nv_bfloat16* __restrict__ dlo)
{
    __shared__ float t[32][33];
    const int b = blockIdx.z;
    const int n0 = blockIdx.x * 32, c0 = blockIdx.y * 32;
    const float* s = src + (size_t)b * CCH * NPIX;
    const int tx = threadIdx.x, ty = threadIdx.y;      // (32, 8)
#pragma unroll
    for (int j = 0; j < 32; j += 8)
        t[ty + j][tx] = s[(size_t)(c0 + ty + j) * NPIX + n0 + tx];
    __syncthreads();
    const size_t base = (size_t)b * NPIX * CCH;
#pragma unroll
    for (int j = 0; j < 32; j += 8) {
        float v = t[tx][ty + j];
        __nv_bfloat16 h = __float2bfloat16(v);
        __nv_bfloat16 l = __float2bfloat16(v - __bfloat162float(h));
        size_t off = base + (size_t)(n0 + ty + j) * CCH + c0 + tx;
        dhi[off] = h; dlo[off] = l;
    }
}

__global__ __launch_bounds__(256)
void transpose_half(const float* __restrict__ src, __half* __restrict__ dst)
{
    __shared__ float t[32][33];
    const int b = blockIdx.z;
    const int n0 = blockIdx.x * 32, c0 = blockIdx.y * 32;
    const float* s = src + (size_t)b * CCH * NPIX;
    const int tx = threadIdx.x, ty = threadIdx.y;      // (32, 8)
#pragma unroll
    for (int j = 0; j < 32; j += 8)
        t[ty + j][tx] = s[(size_t)(c0 + ty + j) * NPIX + n0 + tx];
    __syncthreads();
    const size_t base = (size_t)b * NPIX * CCH;
#pragma unroll
    for (int j = 0; j < 32; j += 8)
        dst[base + (size_t)(n0 + ty + j) * CCH + c0 + tx] = __float2half(t[tx][ty + j]);
}

__global__ __launch_bounds__(256)
void prep_wqk(const float* __restrict__ Wq, const float* __restrict__ bq,
              const float* __restrict__ Wk, const float* __restrict__ bk,
              __nv_bfloat16* __restrict__ whi, __nv_bfloat16* __restrict__ wlo,
              float* __restrict__ bqk)
{
    int i = blockIdx.x * 256 + threadIdx.x;
    float v = (i < DCH * CCH) ? Wq[i] : Wk[i - DCH * CCH];
    __nv_bfloat16 h = __float2bfloat16(v);
    whi[i] = h; wlo[i] = __float2bfloat16(v - __bfloat162float(h));
    if (i < 2 * DCH) bqk[i] = (i < DCH) ? bq[i] : bk[i - DCH];
}

__global__ __launch_bounds__(256)
void prep_wv(const float* __restrict__ Wv,
             __half* __restrict__ whi, __half* __restrict__ wlo)
{
    int i = blockIdx.x * 256 + threadIdx.x;
    float v = Wv[i];
    __half h = __float2half(v);
    whi[i] = h; wlo[i] = __float2half(v - __half2float(h));
}

// ===========================================================================
// Gate: fold 32-way partial-pool reduction + CBAM MLP + sigmoid
// ===========================================================================
__global__ __launch_bounds__(256)
void gate_kernel(const float* __restrict__ ppool,
                 const float* __restrict__ Wca1, const float* __restrict__ Wca2,
                 float* __restrict__ gate)
{
    const int b = blockIdx.x;
    const int tid = threadIdx.x;
    __shared__ float avg_s[CCH], max_s[CCH], h[RCH];

    const float* psum = ppool + (size_t)b * NBLK * CCH;
    const float* pmax = ppool + (size_t)BATCH * NBLK * CCH + (size_t)b * NBLK * CCH;
    for (int c = tid; c < CCH; c += 256) {
        float s = 0.f, m = -FLT_MAX;
#pragma unroll 8
        for (int p = 0; p < NBLK; p++) {
            s += psum[(size_t)p * CCH + c];
            m = fmaxf(m, pmax[(size_t)p * CCH + c]);
        }
        avg_s[c] = s * (1.f / NPIX);
        max_s[c] = m;
    }
    __syncthreads();

    for (int r = tid; r < RCH; r += 256) {
        float s1 = 0.f, s2 = 0.f;
        const float* w = Wca1 + (size_t)r * CCH;
        for (int c = 0; c < CCH; c++) { s1 += w[c] * avg_s[c]; s2 += w[c] * max_s[c]; }
        h[r] = fmaxf(s1, 0.f) + fmaxf(s2, 0.f);
    }
    __syncthreads();

    for (int c = tid; c < CCH; c += 256) {
        float g = 0.f;
        const float* w = Wca2 + (size_t)c * RCH;
#pragma unroll 8
        for (int r = 0; r < RCH; r++) g += w[r] * h[r];
        gate[b * CCH + c] = 1.f / (1.f + expf(-g));
    }
}

__global__ __launch_bounds__(256)
void scale_kernel(const float* __restrict__ outpre, const float* __restrict__ gate,
                  float* __restrict__ out)
{
    size_t i = (size_t)blockIdx.x * 256 + threadIdx.x;
    int row = (int)(i >> 10);
    float g = gate[row];
    float4 v = ((const float4*)outpre)[i];
    v.x *= g; v.y *= g; v.z *= g; v.w *= g;
    ((float4*)out)[i] = v;
}

// ===========================================================================
// Host launcher.  Inputs: x, x1, Wq, bq, Wk, bk, Wv, bv, Wca1, Wca2
// ===========================================================================
extern "C" void kernel_launch(void* const* d_in, const int* in_sizes, int n_in,
                              void* d_out, int out_size)
{
    const float* x    = (const float*)d_in[0];
    const float* x1   = (const float*)d_in[1];
    const float* Wq   = (const float*)d_in[2];
    const float* bq   = (const float*)d_in[3];
    const float* Wk   = (const float*)d_in[4];
    const float* bk   = (const float*)d_in[5];
    const float* Wv   = (const float*)d_in[6];
    const float* bv   = (const float*)d_in[7];
    const float* Wca1 = (const float*)d_in[8];
    const float* Wca2 = (const float*)d_in[9];
    float* out = (float*)d_out;

    constexpr int SM_QK  = StageCfg<0>::BYTES * 2;   // 131072, 1 CTA
    constexpr int SM_ATT = 128 * 132 * 4;            //  67584 (>= 1 stage 65536), 2 CTAs
    constexpr int SM_M1  = StageCfg<1>::BYTES * 2;   //  98304, 2 CTAs

    static cudaStream_t s1 = nullptr;
    static cudaEvent_t evF = nullptr, evJ = nullptr;
    static bool init_done = false;
    if (!init_done) {
        cudaFuncSetAttribute(mma_gemm<1024, 0, false, 0, 2, 1>, cudaFuncAttributeMaxDynamicSharedMemorySize, SM_QK);
        cudaFuncSetAttribute(mma_gemm<128,  2, false, 0, 1, 2>, cudaFuncAttributeMaxDynamicSharedMemorySize, SM_ATT);
        cudaFuncSetAttribute(mma_gemm<1024, 1, false, 1, 2, 2>, cudaFuncAttributeMaxDynamicSharedMemorySize, SM_M1);
        cudaFuncSetAttribute(mma_gemm<4096, 4, true,  1, 2, 2>, cudaFuncAttributeMaxDynamicSharedMemorySize, SM_M1);
        cudaStreamCreateWithFlags(&s1, cudaStreamNonBlocking);
        cudaEventCreateWithFlags(&evF, cudaEventDisableTiming);
        cudaEventCreateWithFlags(&evJ, cudaEventDisableTiming);
        init_done = true;
    }

    void *pxh,*pxl,*p1t,*pwh,*pwl,*pbqk,*pvh,*pvl,*pqh,*pql,*pVh,*pVl,*pat,*pop,*ppp,*pgate;
    cudaGetSymbolAddress(&pxh, g_xThi);  cudaGetSymbolAddress(&pxl, g_xTlo);
    cudaGetSymbolAddress(&p1t, g_x1T);
    cudaGetSymbolAddress(&pwh, g_Wqkhi); cudaGetSymbolAddress(&pwl, g_Wqklo);
    cudaGetSymbolAddress(&pbqk, g_bqk);
    cudaGetSymbolAddress(&pvh, g_Wvhi16); cudaGetSymbolAddress(&pvl, g_Wvlo16);
    cudaGetSymbolAddress(&pqh, g_QKThi); cudaGetSymbolAddress(&pql, g_QKTlo);
    cudaGetSymbolAddress(&pVh, g_Vhi16); cudaGetSymbolAddress(&pVl, g_Vlo16);
    cudaGetSymbolAddress(&pat, g_att16);
    cudaGetSymbolAddress(&pop, g_outpre);
    cudaGetSymbolAddress(&ppp, g_ppool); cudaGetSymbolAddress(&pgate, g_gate);

    dim3 thr(256);
    dim3 tthr(32, 8);

    const long long sXT = (long long)NPIX * CCH;
    const long long sQK = (long long)NPIX * 2 * DCH;
    const long long sV  = (long long)CCH * NPIX;
    const long long sAT = (long long)NPIX * NPIX;

    // ---- fork: V chain on s1 (depends only on x1 / Wv inputs)
    cudaEventRecord(evF, 0);
    cudaStreamWaitEvent(s1, evF, 0);

    transpose_half<<<dim3(NPIX / 32, CCH / 32, BATCH), tthr, 0, s1>>>(x1, (__half*)p1t);
    prep_wv<<<(CCH * CCH) / 256, thr, 0, s1>>>(Wv, (__half*)pvh, (__half*)pvl);
    // V[c][m] = Wv @ x1 + bv   (M=1024, N=4096, K=1024)  fp16 2-term, 2 CTAs/SM
    mma_gemm<1024, 1, false, 1, 2, 2><<<dim3(32, 8, BATCH), thr, SM_M1, s1>>>(
        (const uint16_t*)pvh, (const uint16_t*)pvl, CCH, 0LL,
        (const uint16_t*)p1t, nullptr, CCH, sXT,
        bv, pVh, pVl, NPIX, sV);
    cudaEventRecord(evJ, s1);

    // ---- main stream: QK -> att chain
    transpose_split<<<dim3(NPIX / 32, CCH / 32, BATCH), tthr>>>(x, (__nv_bfloat16*)pxh, (__nv_bfloat16*)pxl);
    prep_wqk<<<(2 * DCH * CCH) / 256, thr>>>(Wq, bq, Wk, bk,
        (__nv_bfloat16*)pwh, (__nv_bfloat16*)pwl, (float*)pbqk);

    // QKT[n][0:256] = xT @ Wqk^T + bqk   (M=4096, N=256, K=1024)  bf16 3-term
    mma_gemm<1024, 0, false, 0, 2, 1><<<dim3(2, 32, BATCH), thr, SM_QK>>>(
        (const uint16_t*)pxh, (const uint16_t*)pxl, CCH, sXT,
        (const uint16_t*)pwh, (const uint16_t*)pwl, CCH, 0LL,
        (const float*)pbqk, pqh, pql, 2 * DCH, sQK);

    // att[n][m] = sigmoid(Q_n . K_m)     (M=4096, N=4096, K=128)  bf16 3-term
    // single-stage, 2 CTAs/SM (co-residency is the pipeline for K=128)
    mma_gemm<128, 2, false, 0, 1, 2><<<dim3(32, 32, BATCH), thr, SM_ATT>>>(
        (const uint16_t*)pqh,       (const uint16_t*)pql,       2 * DCH, sQK,
        (const uint16_t*)pqh + DCH, (const uint16_t*)pql + DCH, 2 * DCH, sQK,
        nullptr, pat, nullptr, NPIX, sAT);

    // ---- join: bmm needs both V and att
    cudaStreamWaitEvent(0, evJ, 0);

    // outpre[c][n] = sum_m V[c][m] att[n][m]  (M=1024, N=4096, K=4096)
    // fp16 2-term, 2 CTAs/SM; SWAP raster; fused partial pooling.
    mma_gemm<4096, 4, true, 1, 2, 2><<<dim3(8, 32, BATCH), thr, SM_M1>>>(
        (const uint16_t*)pVh, (const uint16_t*)pVl, NPIX, sV,
        (const uint16_t*)pat, nullptr, NPIX, sAT,
        nullptr, pop, ppp, NPIX, sV);

    // tail: gate (folds partial reduction) then broadcast scale
    gate_kernel<<<BATCH, thr>>>((const float*)ppp, Wca1, Wca2, (float*)pgate);
    scale_kernel<<<(int)(((size_t)BATCH * CCH * NPIX / 4) / 256), thr>>>(
        (const float*)pop, (const float*)pgate, out);
}